// round 1
// baseline (speedup 1.0000x reference)
#include <cuda_runtime.h>

#define NN 500000
#define NE 1250000
#define HID 64
#define NG 512
#define NC 10

#define SCAN_T 256
#define SCAN_I 4
#define SCAN_B (SCAN_T*SCAN_I)   // 1024
#define POOL_CHUNK 512

// ---------------- device scratch (static globals; no allocation) ----------------
__device__ int      g_idx64;
__device__ int      d_degE[NN];
__device__ float    d_dinv[NN];
__device__ int      d_rowptr[NN];
__device__ int      d_cursor[NN];
__device__ int      d_bsums[512];
__device__ int      d_col[NE];
__device__ float    d_w[NE];
__device__ float    d_hbuf[(size_t)NN*HID];
__device__ float    d_tbuf[(size_t)NN*HID];
__device__ float    d_gsum[NG*HID];
__device__ unsigned d_gmax[NG*HID];
__device__ int      d_cnt[NG];

__device__ __forceinline__ long long ld_idx(const void* p, long long j, int is64) {
    if (is64) return ((const long long*)p)[j];
    return (long long)((const int*)p)[j];
}

// ---------------- index-width detection ----------------
// If buffer holds int64 values < 2^31, every odd 32-bit word is 0.
// If it holds int32 node ids (random in [0,500000)), 2048 samples OR to nonzero.
__global__ void detect_kernel(const unsigned* __restrict__ p) {
    __shared__ unsigned red[256];
    int t = threadIdx.x;
    unsigned v = 0;
    for (int i = 2 * t + 1; i < 4096; i += 512) v |= p[i];
    red[t] = v;
    __syncthreads();
    for (int off = 128; off > 0; off >>= 1) {
        if (t < off) red[t] |= red[t + off];
        __syncthreads();
    }
    if (t == 0) g_idx64 = (red[0] == 0) ? 1 : 0;
}

// ---------------- zeroing ----------------
__global__ void zero_kernel(int n) {
    int i = blockIdx.x * blockDim.x + threadIdx.x;
    if (i < n) d_degE[i] = 0;
    if (i < NG * HID) { d_gsum[i] = 0.f; d_gmax[i] = 0u; }
    if (i < NG) d_cnt[i] = 0;
}

// ---------------- degree histogram over dst ----------------
__global__ void hist_kernel(const void* __restrict__ ei, int E) {
    int e = blockIdx.x * blockDim.x + threadIdx.x;
    if (e >= E) return;
    int is64 = g_idx64;
    long long dd = ld_idx(ei, (long long)E + e, is64);
    atomicAdd(&d_degE[(int)dd], 1);
}

__global__ void dinv_kernel(int n) {
    int i = blockIdx.x * blockDim.x + threadIdx.x;
    if (i < n) d_dinv[i] = rsqrtf((float)d_degE[i] + 1.0f);  // +1 self-loop
}

// ---------------- exclusive scan (3 kernels) ----------------
__global__ void scanA_kernel(int n) {
    __shared__ int sm[SCAN_T];
    int b = blockIdx.x, t = threadIdx.x;
    int base = b * SCAN_B + t * SCAN_I;
    int v[SCAN_I];
    int s = 0;
#pragma unroll
    for (int j = 0; j < SCAN_I; j++) {
        v[j] = (base + j < n) ? d_degE[base + j] : 0;
        s += v[j];
    }
    sm[t] = s;
    __syncthreads();
    for (int off = 1; off < SCAN_T; off <<= 1) {
        int x = (t >= off) ? sm[t - off] : 0;
        __syncthreads();
        sm[t] += x;
        __syncthreads();
    }
    int excl = (t > 0) ? sm[t - 1] : 0;
    if (t == SCAN_T - 1) d_bsums[b] = sm[t];
    int run = excl;
#pragma unroll
    for (int j = 0; j < SCAN_I; j++) {
        if (base + j < n) d_rowptr[base + j] = run;
        run += v[j];
    }
}

__global__ void scanB_kernel(int nb) {
    __shared__ int sm[512];
    int t = threadIdx.x;
    sm[t] = (t < nb) ? d_bsums[t] : 0;
    __syncthreads();
    for (int off = 1; off < 512; off <<= 1) {
        int x = (t >= off) ? sm[t - off] : 0;
        __syncthreads();
        sm[t] += x;
        __syncthreads();
    }
    int excl = (t > 0) ? sm[t - 1] : 0;
    if (t < nb) d_bsums[t] = excl;
}

__global__ void scanC_kernel(int n) {
    int i = blockIdx.x * blockDim.x + threadIdx.x;
    if (i < n) {
        int v = d_rowptr[i] + d_bsums[i / SCAN_B];
        d_rowptr[i] = v;
        d_cursor[i] = v;
    }
}

// ---------------- CSR scatter ----------------
__global__ void scatter_kernel(const void* __restrict__ ei, int E) {
    int e = blockIdx.x * blockDim.x + threadIdx.x;
    if (e >= E) return;
    int is64 = g_idx64;
    long long ss = ld_idx(ei, e, is64);
    long long dd = ld_idx(ei, (long long)E + e, is64);
    int pos = atomicAdd(&d_cursor[(int)dd], 1);
    d_col[pos] = (int)ss;
    d_w[pos] = d_dinv[(int)ss];
}

// ---------------- dense GEMM: out[N,64] = in[N,K] @ W[K,64] ----------------
// 256 threads, block tile 64 rows x 64 cols, per-thread 4x4.
template <int K>
__global__ void gemm_kernel(const float* __restrict__ in, const float* __restrict__ W,
                            float* __restrict__ out, int n) {
    extern __shared__ float sm[];
    float* Asm = sm;                 // [K][68] transposed, padded
    float* Wsm = sm + K * 68;        // [K][64]
    int tid = threadIdx.x;
    int rb = blockIdx.x * 64;

    for (int i = tid; i < K * 64; i += 256) Wsm[i] = W[i];
    for (int i = tid; i < 64 * K; i += 256) {
        int r = i / K, k = i % K;
        float v = (rb + r < n) ? in[(size_t)(rb + r) * K + k] : 0.f;
        Asm[k * 68 + r] = v;
    }
    __syncthreads();

    int tx = tid % 16, ty = tid / 16;
    float acc[4][4] = {};
#pragma unroll 8
    for (int k = 0; k < K; k++) {
        const float4 a  = *(const float4*)(Asm + k * 68 + ty * 4);
        const float4 wv = *(const float4*)(Wsm + k * 64 + tx * 4);
        acc[0][0] += a.x * wv.x; acc[0][1] += a.x * wv.y; acc[0][2] += a.x * wv.z; acc[0][3] += a.x * wv.w;
        acc[1][0] += a.y * wv.x; acc[1][1] += a.y * wv.y; acc[1][2] += a.y * wv.z; acc[1][3] += a.y * wv.w;
        acc[2][0] += a.z * wv.x; acc[2][1] += a.z * wv.y; acc[2][2] += a.z * wv.z; acc[2][3] += a.z * wv.w;
        acc[3][0] += a.w * wv.x; acc[3][1] += a.w * wv.y; acc[3][2] += a.w * wv.z; acc[3][3] += a.w * wv.w;
    }
#pragma unroll
    for (int j = 0; j < 4; j++) {
        int r = rb + ty * 4 + j;
        if (r < n) {
            float4 o = make_float4(acc[j][0], acc[j][1], acc[j][2], acc[j][3]);
            *(float4*)(out + (size_t)r * HID + tx * 4) = o;
        }
    }
}

// ---------------- sparse aggregation (+ self loop, bias, relu) ----------------
// h[i] = relu(dinv[i] * (sum_e w[e]*t[col[e]] + dinv[i]*t[i]) + b)
__global__ void aggregate_kernel(const float* __restrict__ t, const float* __restrict__ b,
                                 float* __restrict__ h, int n) {
    int i = blockIdx.x * blockDim.y + threadIdx.y;
    int c = threadIdx.x;  // 64 channels
    if (i >= n) return;
    float di = d_dinv[i];
    float acc = di * t[(size_t)i * HID + c];
    int start = d_rowptr[i];
    int cnt = d_degE[i];
    for (int j = 0; j < cnt; j++) {
        int s = d_col[start + j];
        acc += d_w[start + j] * t[(size_t)s * HID + c];
    }
    float v = di * acc + b[c];
    h[(size_t)i * HID + c] = fmaxf(v, 0.f);
}

// ---------------- pooling (batch_index is sorted -> run-length local accum) ----------------
__global__ void pool_kernel(const float* __restrict__ h, const void* __restrict__ batch, int n) {
    int is64 = g_idx64;
    int c = threadIdx.x;  // 64
    int base = blockIdx.x * POOL_CHUNK;
    int end = min(base + POOL_CHUNK, n);
    int curg = -1, lc = 0;
    float ls = 0.f, lm = 0.f;
    for (int i = base; i < end; i++) {
        int g = (int)ld_idx(batch, i, is64);
        if (g != curg) {
            if (curg >= 0) {
                atomicAdd(&d_gsum[curg * HID + c], ls);
                atomicMax(&d_gmax[curg * HID + c], __float_as_uint(lm));
                if (c == 0) atomicAdd(&d_cnt[curg], lc);
            }
            curg = g; ls = 0.f; lm = 0.f; lc = 0;
        }
        float v = h[(size_t)i * HID + c];
        ls += v;
        lm = fmaxf(lm, v);
        lc++;
    }
    if (curg >= 0) {
        atomicAdd(&d_gsum[curg * HID + c], ls);
        atomicMax(&d_gmax[curg * HID + c], __float_as_uint(lm));
        if (c == 0) atomicAdd(&d_cnt[curg], lc);
    }
}

// ---------------- final: [mean | max] @ Wout + bout ----------------
__global__ void final_kernel(const float* __restrict__ Wout, const float* __restrict__ bout,
                             float* __restrict__ out) {
    __shared__ float p[2 * HID];
    int g = blockIdx.x;
    int t = threadIdx.x;  // 128
    if (t < HID) {
        float cn = fmaxf((float)d_cnt[g], 1.f);
        p[t] = d_gsum[g * HID + t] / cn;
        p[HID + t] = __uint_as_float(d_gmax[g * HID + t]);
    }
    __syncthreads();
    if (t < NC) {
        float a = bout[t];
#pragma unroll 16
        for (int k = 0; k < 2 * HID; k++) a += p[k] * Wout[k * NC + t];
        out[g * NC + t] = a;
    }
}

// ---------------- launch ----------------
extern "C" void kernel_launch(void* const* d_in, const int* in_sizes, int n_in,
                              void* d_out, int out_size) {
    const float* x    = (const float*)d_in[0];
    const void*  ei   = d_in[1];
    const void*  bat  = d_in[2];
    const float* W0   = (const float*)d_in[3];
    const float* b0   = (const float*)d_in[4];
    const float* W1   = (const float*)d_in[5];
    const float* b1   = (const float*)d_in[6];
    const float* W2   = (const float*)d_in[7];
    const float* b2   = (const float*)d_in[8];
    const float* Wout = (const float*)d_in[9];
    const float* bout = (const float*)d_in[10];
    float* out = (float*)d_out;

    int N = in_sizes[2];          // node count (element count, dtype-independent)
    int E = in_sizes[1] / 2;

    float *hp, *tp;
    cudaGetSymbolAddress((void**)&hp, d_hbuf);
    cudaGetSymbolAddress((void**)&tp, d_tbuf);

    int smem128 = (128 * 68 + 128 * 64) * 4;
    int smem64  = (64 * 68 + 64 * 64) * 4;
    cudaFuncSetAttribute(gemm_kernel<128>, cudaFuncAttributeMaxDynamicSharedMemorySize, smem128);
    cudaFuncSetAttribute(gemm_kernel<64>,  cudaFuncAttributeMaxDynamicSharedMemorySize, smem64);

    detect_kernel<<<1, 256>>>((const unsigned*)ei);
    zero_kernel<<<(N + 255) / 256, 256>>>(N);
    hist_kernel<<<(E + 255) / 256, 256>>>(ei, E);
    dinv_kernel<<<(N + 255) / 256, 256>>>(N);

    int nb = (N + SCAN_B - 1) / SCAN_B;
    scanA_kernel<<<nb, SCAN_T>>>(N);
    scanB_kernel<<<1, 512>>>(nb);
    scanC_kernel<<<(N + 255) / 256, 256>>>(N);
    scatter_kernel<<<(E + 255) / 256, 256>>>(ei, E);

    int gblk = (N + 63) / 64;
    dim3 aggB(64, 4);
    int aggG = (N + 3) / 4;

    // layer 0: t = x @ W0 ; h = relu(agg(t) + b0)
    gemm_kernel<128><<<gblk, 256, smem128>>>(x, W0, tp, N);
    aggregate_kernel<<<aggG, aggB>>>(tp, b0, hp, N);
    // layer 1
    gemm_kernel<64><<<gblk, 256, smem64>>>(hp, W1, tp, N);
    aggregate_kernel<<<aggG, aggB>>>(tp, b1, hp, N);
    // layer 2
    gemm_kernel<64><<<gblk, 256, smem64>>>(hp, W2, tp, N);
    aggregate_kernel<<<aggG, aggB>>>(tp, b2, hp, N);

    pool_kernel<<<(N + POOL_CHUNK - 1) / POOL_CHUNK, 64>>>(hp, bat, N);
    final_kernel<<<NG, 128>>>(Wout, bout, out);
}

// round 4
// speedup vs baseline: 1.4031x; 1.4031x over previous
#include <cuda_runtime.h>
#include <cuda_bf16.h>
#include <cstdint>

#define NN 500000
#define NE 1250000
#define HID 64
#define NG 512
#define NC 10

#define SCAN_T 256
#define SCAN_I 4
#define SCAN_B (SCAN_T*SCAN_I)   // 1024
#define POOL_CHUNK 512

// ---------------- device scratch ----------------
__device__ int      g_idx64;
__device__ int      d_degE[NN];
__device__ float    d_dinv[NN];
__device__ int      d_rowptr[NN];
__device__ int      d_cursor[NN];
__device__ int      d_bsums[512];
__device__ int      d_col[NE];
__device__ float    d_w[NE];
__device__ float    d_hbuf[(size_t)NN*HID];
__device__ float    d_tbuf[(size_t)NN*HID];
__device__ float    d_gsum[NG*HID];
__device__ unsigned d_gmax[NG*HID];
__device__ int      d_cnt[NG];

__device__ __forceinline__ int ld_idx32(const void* p, long long j, int is64) {
    const unsigned* u = (const unsigned*)p;
    return (int)(is64 ? u[2*j] : u[j]);
}

// ---------------- index-width detection ----------------
__global__ void detect_kernel(const unsigned* __restrict__ p) {
    __shared__ unsigned red[256];
    int t = threadIdx.x;
    unsigned v = 0;
    for (int i = 2 * t + 1; i < 4096; i += 512) v |= p[i];
    red[t] = v;
    __syncthreads();
    for (int off = 128; off > 0; off >>= 1) {
        if (t < off) red[t] |= red[t + off];
        __syncthreads();
    }
    if (t == 0) g_idx64 = (red[0] == 0) ? 1 : 0;
}

__global__ void zero_kernel(int n) {
    int i = blockIdx.x * blockDim.x + threadIdx.x;
    if (i < n) d_degE[i] = 0;
    if (i < NG * HID) { d_gsum[i] = 0.f; d_gmax[i] = 0u; }
    if (i < NG) d_cnt[i] = 0;
}

__global__ void hist_kernel(const void* __restrict__ ei, int E) {
    int e = blockIdx.x * blockDim.x + threadIdx.x;
    if (e >= E) return;
    int dd = ld_idx32(ei, (long long)E + e, g_idx64);
    atomicAdd(&d_degE[dd], 1);
}

__global__ void dinv_kernel(int n) {
    int i = blockIdx.x * blockDim.x + threadIdx.x;
    if (i < n) d_dinv[i] = rsqrtf((float)d_degE[i] + 1.0f);
}

// ---------------- exclusive scan ----------------
__global__ void scanA_kernel(int n) {
    __shared__ int sm[SCAN_T];
    int b = blockIdx.x, t = threadIdx.x;
    int base = b * SCAN_B + t * SCAN_I;
    int v[SCAN_I];
    int s = 0;
#pragma unroll
    for (int j = 0; j < SCAN_I; j++) {
        v[j] = (base + j < n) ? d_degE[base + j] : 0;
        s += v[j];
    }
    sm[t] = s;
    __syncthreads();
    for (int off = 1; off < SCAN_T; off <<= 1) {
        int x = (t >= off) ? sm[t - off] : 0;
        __syncthreads();
        sm[t] += x;
        __syncthreads();
    }
    int excl = (t > 0) ? sm[t - 1] : 0;
    if (t == SCAN_T - 1) d_bsums[b] = sm[t];
    int run = excl;
#pragma unroll
    for (int j = 0; j < SCAN_I; j++) {
        if (base + j < n) d_rowptr[base + j] = run;
        run += v[j];
    }
}

__global__ void scanB_kernel(int nb) {
    __shared__ int sm[512];
    int t = threadIdx.x;
    sm[t] = (t < nb) ? d_bsums[t] : 0;
    __syncthreads();
    for (int off = 1; off < 512; off <<= 1) {
        int x = (t >= off) ? sm[t - off] : 0;
        __syncthreads();
        sm[t] += x;
        __syncthreads();
    }
    int excl = (t > 0) ? sm[t - 1] : 0;
    if (t < nb) d_bsums[t] = excl;
}

__global__ void scanC_kernel(int n) {
    int i = blockIdx.x * blockDim.x + threadIdx.x;
    if (i < n) {
        int v = d_rowptr[i] + d_bsums[i / SCAN_B];
        d_rowptr[i] = v;
        d_cursor[i] = v;
    }
}

__global__ void scatter_kernel(const void* __restrict__ ei, int E) {
    int e = blockIdx.x * blockDim.x + threadIdx.x;
    if (e >= E) return;
    int is64 = g_idx64;
    int ss = ld_idx32(ei, e, is64);
    int dd = ld_idx32(ei, (long long)E + e, is64);
    int pos = atomicAdd(&d_cursor[dd], 1);
    d_col[pos] = ss;
    d_w[pos] = d_dinv[ss];
}

// ---------------- bf16x2 split helpers ----------------
__device__ __forceinline__ void split2(float v0, float v1, uint32_t& hi, uint32_t& lo) {
    __nv_bfloat16 h0 = __float2bfloat16(v0);
    __nv_bfloat16 h1 = __float2bfloat16(v1);
    __nv_bfloat16 l0 = __float2bfloat16(v0 - __bfloat162float(h0));
    __nv_bfloat16 l1 = __float2bfloat16(v1 - __bfloat162float(h1));
    hi = (uint32_t)__bfloat16_as_ushort(h0) | ((uint32_t)__bfloat16_as_ushort(h1) << 16);
    lo = (uint32_t)__bfloat16_as_ushort(l0) | ((uint32_t)__bfloat16_as_ushort(l1) << 16);
}

#define MMA_BF16(c, a, b0v, b1v) \
    asm volatile("mma.sync.aligned.m16n8k16.row.col.f32.bf16.bf16.f32 " \
        "{%0,%1,%2,%3}, {%4,%5,%6,%7}, {%8,%9}, {%0,%1,%2,%3};" \
        : "+f"((c)[0]), "+f"((c)[1]), "+f"((c)[2]), "+f"((c)[3]) \
        : "r"((a)[0]), "r"((a)[1]), "r"((a)[2]), "r"((a)[3]), "r"(b0v), "r"(b1v))

// ---------------- HMMA GEMM: out[N,64] = in[N,K] @ W[K,64], fp32 via bf16 split ----------------
// CTA: 256 threads (8 warps), 128 rows x 64 cols. Warp w: rows 16w..16w+15.
// D = Ahi*Whi + Ahi*Wlo + Alo*Whi (fp32 register accumulators)
template <int K>
__global__ void __launch_bounds__(256, 2) gemm_mma(const float* __restrict__ in,
                                                   const float* __restrict__ W,
                                                   float* __restrict__ out, int n) {
    constexpr int K2 = K / 2;       // words per row
    constexpr int AST = K2 + 4;     // A row stride (words)
    constexpr int WST = 72;         // W row stride (words)
    constexpr int NKC = K / 16;     // k chunks

    extern __shared__ uint32_t sm[];
    uint32_t* Ah = sm;                       // [128][AST]
    uint32_t* Al = Ah + 128 * AST;
    uint32_t* Wh = Al + 128 * AST;           // [K2][WST]
    uint32_t* Wl = Wh + K2 * WST;

    int tid = threadIdx.x, wid = tid >> 5, lane = tid & 31;
    int rb = blockIdx.x * 128;
    int nrows = min(128, n - rb);

    // pack W: word k2 holds (W[2k2][nn], W[2k2+1][nn])
    for (int i = tid; i < K2 * 64; i += 256) {
        int k2 = i >> 6, nn = i & 63;
        float v0 = W[(2 * k2) * 64 + nn];
        float v1 = W[(2 * k2 + 1) * 64 + nn];
        uint32_t hi, lo;
        split2(v0, v1, hi, lo);
        Wh[k2 * WST + nn] = hi;
        Wl[k2 * WST + nn] = lo;
    }
    // pack A rows (float2 coalesced loads)
    for (int i = tid; i < 128 * K2; i += 256) {
        int r = i / K2, j = i % K2;
        float2 v = (r < nrows) ? __ldg((const float2*)(in + (size_t)(rb + r) * K) + j)
                               : make_float2(0.f, 0.f);
        uint32_t hi, lo;
        split2(v.x, v.y, hi, lo);
        Ah[r * AST + j] = hi;
        Al[r * AST + j] = lo;
    }
    __syncthreads();

    int qr = lane >> 2, qc = lane & 3;       // quad row / col
    int r0 = wid * 16 + qr;
    float acc[8][4];
#pragma unroll
    for (int t = 0; t < 8; t++)
#pragma unroll
        for (int j = 0; j < 4; j++) acc[t][j] = 0.f;

#pragma unroll
    for (int kc = 0; kc < NKC; kc++) {
        int ab = r0 * AST + kc * 8 + qc;
        uint32_t ah[4], al[4];
        ah[0] = Ah[ab];             ah[1] = Ah[ab + 8 * AST];
        ah[2] = Ah[ab + 4];         ah[3] = Ah[ab + 8 * AST + 4];
        al[0] = Al[ab];             al[1] = Al[ab + 8 * AST];
        al[2] = Al[ab + 4];         al[3] = Al[ab + 8 * AST + 4];
        int bb = (kc * 8 + qc) * WST + qr;
#pragma unroll
        for (int t = 0; t < 8; t++) {
            uint32_t bh0 = Wh[bb + 8 * t];
            uint32_t bh1 = Wh[bb + 4 * WST + 8 * t];
            uint32_t bl0 = Wl[bb + 8 * t];
            uint32_t bl1 = Wl[bb + 4 * WST + 8 * t];
            MMA_BF16(acc[t], ah, bh0, bh1);
            MMA_BF16(acc[t], ah, bl0, bl1);
            MMA_BF16(acc[t], al, bh0, bh1);
        }
    }

    // direct global store: for fixed (t,qr), 4 qc-lanes fill one 32B sector
    bool ok0 = (r0 < nrows), ok1 = (r0 + 8 < nrows);
    float* o0 = out + (size_t)(rb + r0) * 64;
    float* o1 = out + (size_t)(rb + r0 + 8) * 64;
#pragma unroll
    for (int t = 0; t < 8; t++) {
        int c = 8 * t + qc * 2;
        if (ok0) *(float2*)(o0 + c) = make_float2(acc[t][0], acc[t][1]);
        if (ok1) *(float2*)(o1 + c) = make_float2(acc[t][2], acc[t][3]);
    }
}

// ---------------- sparse aggregation: warp per node, float2 per lane ----------------
__global__ void aggregate_kernel(const float* __restrict__ t, const float* __restrict__ b,
                                 float* __restrict__ h, int n) {
    int i = blockIdx.x * blockDim.y + threadIdx.y;
    if (i >= n) return;
    int c2 = threadIdx.x;  // channels 2c2, 2c2+1
    float2 bb = __ldg((const float2*)b + c2);
    float di = d_dinv[i];
    float2 v = __ldg((const float2*)(t + (size_t)i * HID) + c2);
    float ax = di * v.x, ay = di * v.y;
    int start = d_rowptr[i];
    int cnt = d_degE[i];
    for (int j = 0; j < cnt; j++) {
        int s = d_col[start + j];
        float w = d_w[start + j];
        float2 u = __ldg((const float2*)(t + (size_t)s * HID) + c2);
        ax += w * u.x; ay += w * u.y;
    }
    float2 o = make_float2(fmaxf(di * ax + bb.x, 0.f), fmaxf(di * ay + bb.y, 0.f));
    ((float2*)(h + (size_t)i * HID))[c2] = o;
}

// ---------------- pooling (sorted batch_index -> run-length local accum) ----------------
__global__ void pool_kernel(const float* __restrict__ h, const void* __restrict__ batch, int n) {
    int is64 = g_idx64;
    int c = threadIdx.x;  // 64
    int base = blockIdx.x * POOL_CHUNK;
    int end = min(base + POOL_CHUNK, n);
    int curg = -1, lc = 0;
    float ls = 0.f, lm = 0.f;
    for (int i = base; i < end; i++) {
        int g = ld_idx32(batch, i, is64);
        if (g != curg) {
            if (curg >= 0) {
                atomicAdd(&d_gsum[curg * HID + c], ls);
                atomicMax(&d_gmax[curg * HID + c], __float_as_uint(lm));
                if (c == 0) atomicAdd(&d_cnt[curg], lc);
            }
            curg = g; ls = 0.f; lm = 0.f; lc = 0;
        }
        float v = h[(size_t)i * HID + c];
        ls += v;
        lm = fmaxf(lm, v);
        lc++;
    }
    if (curg >= 0) {
        atomicAdd(&d_gsum[curg * HID + c], ls);
        atomicMax(&d_gmax[curg * HID + c], __float_as_uint(lm));
        if (c == 0) atomicAdd(&d_cnt[curg], lc);
    }
}

// ---------------- final ----------------
__global__ void final_kernel(const float* __restrict__ Wout, const float* __restrict__ bout,
                             float* __restrict__ out) {
    __shared__ float p[2 * HID];
    int g = blockIdx.x;
    int t = threadIdx.x;  // 128
    if (t < HID) {
        float cn = fmaxf((float)d_cnt[g], 1.f);
        p[t] = d_gsum[g * HID + t] / cn;
        p[HID + t] = __uint_as_float(d_gmax[g * HID + t]);
    }
    __syncthreads();
    if (t < NC) {
        float a = bout[t];
#pragma unroll 16
        for (int k = 0; k < 2 * HID; k++) a += p[k] * Wout[k * NC + t];
        out[g * NC + t] = a;
    }
}

// ---------------- launch ----------------
extern "C" void kernel_launch(void* const* d_in, const int* in_sizes, int n_in,
                              void* d_out, int out_size) {
    const float* x    = (const float*)d_in[0];
    const void*  ei   = d_in[1];
    const void*  bat  = d_in[2];
    const float* W0   = (const float*)d_in[3];
    const float* b0   = (const float*)d_in[4];
    const float* W1   = (const float*)d_in[5];
    const float* b1   = (const float*)d_in[6];
    const float* W2   = (const float*)d_in[7];
    const float* b2   = (const float*)d_in[8];
    const float* Wout = (const float*)d_in[9];
    const float* bout = (const float*)d_in[10];
    float* out = (float*)d_out;

    int N = in_sizes[2];
    int E = in_sizes[1] / 2;

    float *hp, *tp;
    cudaGetSymbolAddress((void**)&hp, d_hbuf);
    cudaGetSymbolAddress((void**)&tp, d_tbuf);

    // smem: 2 A tiles [128][K/2+4] + 2 W tiles [K/2][72] (uint32)
    int smem128 = (2 * 128 * (64 + 4) + 2 * 64 * 72) * 4;  // 106496
    int smem64  = (2 * 128 * (32 + 4) + 2 * 32 * 72) * 4;  // 55296
    cudaFuncSetAttribute(gemm_mma<128>, cudaFuncAttributeMaxDynamicSharedMemorySize, smem128);
    cudaFuncSetAttribute(gemm_mma<64>,  cudaFuncAttributeMaxDynamicSharedMemorySize, smem64);

    int gblk = (N + 127) / 128;
    dim3 aggB(32, 8);
    int aggG = (N + 7) / 8;

    detect_kernel<<<1, 256>>>((const unsigned*)ei);
    zero_kernel<<<(N + 255) / 256, 256>>>(N);
    hist_kernel<<<(E + 255) / 256, 256>>>(ei, E);
    gemm_mma<128><<<gblk, 256, smem128>>>(x, W0, tp, N);   // 4th launch -> profiled slot
    dinv_kernel<<<(N + 255) / 256, 256>>>(N);

    int nb = (N + SCAN_B - 1) / SCAN_B;
    scanA_kernel<<<nb, SCAN_T>>>(N);
    scanB_kernel<<<1, 512>>>(nb);
    scanC_kernel<<<(N + 255) / 256, 256>>>(N);
    scatter_kernel<<<(E + 255) / 256, 256>>>(ei, E);

    aggregate_kernel<<<aggG, aggB>>>(tp, b0, hp, N);
    gemm_mma<64><<<gblk, 256, smem64>>>(hp, W1, tp, N);
    aggregate_kernel<<<aggG, aggB>>>(tp, b1, hp, N);
    gemm_mma<64><<<gblk, 256, smem64>>>(hp, W2, tp, N);
    aggregate_kernel<<<aggG, aggB>>>(tp, b2, hp, N);

    pool_kernel<<<(N + POOL_CHUNK - 1) / POOL_CHUNK, 64>>>(hp, bat, N);
    final_kernel<<<NG, 128>>>(Wout, bout, out);
}

// round 5
// speedup vs baseline: 1.8038x; 1.2856x over previous
#include <cuda_runtime.h>
#include <cuda_bf16.h>
#include <cstdint>

#define NN 500000
#define NE 1250000
#define HID 64
#define NG 512
#define NC 10

#define SCAN_T 256
#define SCAN_I 4
#define SCAN_B (SCAN_T*SCAN_I)   // 1024
#define POOL_CHUNK 512

// ---------------- device scratch ----------------
__device__ int      g_idx64;
__device__ int      d_degE[NN];
__device__ float    d_dinv[NN];
__device__ int      d_rowptr[NN];
__device__ int      d_cursor[NN];
__device__ int      d_bsums[512];
__device__ int      d_col[NE];
__device__ float    d_w[NE];
__device__ float    d_hbuf[(size_t)NN*HID];
__device__ float    d_tbuf[(size_t)NN*HID];
__device__ float    d_gsum[NG*HID];
__device__ unsigned d_gmax[NG*HID];
__device__ int      d_cnt[NG];

__device__ __forceinline__ int ld_idx32(const void* p, long long j, int is64) {
    const unsigned* u = (const unsigned*)p;
    return (int)(is64 ? u[2*j] : u[j]);
}

// ---------------- index-width detection ----------------
__global__ void detect_kernel(const unsigned* __restrict__ p) {
    __shared__ unsigned red[256];
    int t = threadIdx.x;
    unsigned v = 0;
    for (int i = 2 * t + 1; i < 4096; i += 512) v |= p[i];
    red[t] = v;
    __syncthreads();
    for (int off = 128; off > 0; off >>= 1) {
        if (t < off) red[t] |= red[t + off];
        __syncthreads();
    }
    if (t == 0) g_idx64 = (red[0] == 0) ? 1 : 0;
}

__global__ void zero_kernel(int n) {
    int i = blockIdx.x * blockDim.x + threadIdx.x;
    if (i < n) d_degE[i] = 0;
    if (i < NG * HID) { d_gsum[i] = 0.f; d_gmax[i] = 0u; }
    if (i < NG) d_cnt[i] = 0;
}

__global__ void hist_kernel(const void* __restrict__ ei, int E) {
    int e = blockIdx.x * blockDim.x + threadIdx.x;
    if (e >= E) return;
    int dd = ld_idx32(ei, (long long)E + e, g_idx64);
    atomicAdd(&d_degE[dd], 1);
}

__global__ void dinv_kernel(int n) {
    int i = blockIdx.x * blockDim.x + threadIdx.x;
    if (i < n) d_dinv[i] = rsqrtf((float)d_degE[i] + 1.0f);
}

// ---------------- exclusive scan ----------------
__global__ void scanA_kernel(int n) {
    __shared__ int sm[SCAN_T];
    int b = blockIdx.x, t = threadIdx.x;
    int base = b * SCAN_B + t * SCAN_I;
    int v[SCAN_I];
    int s = 0;
#pragma unroll
    for (int j = 0; j < SCAN_I; j++) {
        v[j] = (base + j < n) ? d_degE[base + j] : 0;
        s += v[j];
    }
    sm[t] = s;
    __syncthreads();
    for (int off = 1; off < SCAN_T; off <<= 1) {
        int x = (t >= off) ? sm[t - off] : 0;
        __syncthreads();
        sm[t] += x;
        __syncthreads();
    }
    int excl = (t > 0) ? sm[t - 1] : 0;
    if (t == SCAN_T - 1) d_bsums[b] = sm[t];
    int run = excl;
#pragma unroll
    for (int j = 0; j < SCAN_I; j++) {
        if (base + j < n) d_rowptr[base + j] = run;
        run += v[j];
    }
}

__global__ void scanB_kernel(int nb) {
    __shared__ int sm[512];
    int t = threadIdx.x;
    sm[t] = (t < nb) ? d_bsums[t] : 0;
    __syncthreads();
    for (int off = 1; off < 512; off <<= 1) {
        int x = (t >= off) ? sm[t - off] : 0;
        __syncthreads();
        sm[t] += x;
        __syncthreads();
    }
    int excl = (t > 0) ? sm[t - 1] : 0;
    if (t < nb) d_bsums[t] = excl;
}

__global__ void scanC_kernel(int n) {
    int i = blockIdx.x * blockDim.x + threadIdx.x;
    if (i < n) {
        int v = d_rowptr[i] + d_bsums[i / SCAN_B];
        d_rowptr[i] = v;
        d_cursor[i] = v;
    }
}

__global__ void scatter_kernel(const void* __restrict__ ei, int E) {
    int e = blockIdx.x * blockDim.x + threadIdx.x;
    if (e >= E) return;
    int is64 = g_idx64;
    int ss = ld_idx32(ei, e, is64);
    int dd = ld_idx32(ei, (long long)E + e, is64);
    int pos = atomicAdd(&d_cursor[dd], 1);
    d_col[pos] = ss;
    d_w[pos] = d_dinv[ss];
}

// ---------------- fast bf16x2 split: 1 pack-cvt + bitops + 1 pack-cvt ----------------
__device__ __forceinline__ void split2(float v0, float v1, uint32_t& hi, uint32_t& lo) {
    uint32_t h;
    asm("cvt.rn.bf16x2.f32 %0, %1, %2;" : "=r"(h) : "f"(v1), "f"(v0));
    float f0 = __uint_as_float(h << 16);
    float f1 = __uint_as_float(h & 0xFFFF0000u);
    asm("cvt.rn.bf16x2.f32 %0, %1, %2;" : "=r"(lo) : "f"(v1 - f1), "f"(v0 - f0));
    hi = h;
}

#define MMA_BF16(c, a, b0v, b1v) \
    asm volatile("mma.sync.aligned.m16n8k16.row.col.f32.bf16.bf16.f32 " \
        "{%0,%1,%2,%3}, {%4,%5,%6,%7}, {%8,%9}, {%0,%1,%2,%3};" \
        : "+f"((c)[0]), "+f"((c)[1]), "+f"((c)[2]), "+f"((c)[3]) \
        : "r"((a)[0]), "r"((a)[1]), "r"((a)[2]), "r"((a)[3]), "r"(b0v), "r"(b1v))

// ---------------- HMMA GEMM: out[N,64] = in[N,K] @ W[K,64], fp32 via bf16 split ----------------
// 256 threads / 8 warps; warp w owns rows 16w..16w+15; A fragments loaded
// directly from gmem (exclusive per warp, full 32B sectors), converted in-register.
// W (shared) packed hi/lo in smem. D = Ahi*Whi + Ahi*Wlo + Alo*Whi.
template <int K>
__global__ void __launch_bounds__(256, 2) gemm_mma(const float* __restrict__ in,
                                                   const float* __restrict__ W,
                                                   float* __restrict__ out, int n) {
    constexpr int K2 = K / 2;
    constexpr int WST = 72;         // bank (8*qc + qr + 8*t) mod 32 -> conflict-free
    constexpr int NKC = K / 16;

    __shared__ uint32_t Wh[K2 * WST];
    __shared__ uint32_t Wl[K2 * WST];

    int tid = threadIdx.x, wid = tid >> 5, lane = tid & 31;
    int rb = blockIdx.x * 128;
    int nrows = min(128, n - rb);

    // pack W: word k2 = (W[2k2][nn], W[2k2+1][nn])
    for (int i = tid; i < K2 * 64; i += 256) {
        int k2 = i >> 6, nn = i & 63;
        uint32_t hi, lo;
        split2(W[(2 * k2) * 64 + nn], W[(2 * k2 + 1) * 64 + nn], hi, lo);
        Wh[k2 * WST + nn] = hi;
        Wl[k2 * WST + nn] = lo;
    }
    __syncthreads();

    int qr = lane >> 2, qc = lane & 3;
    int r0 = wid * 16 + qr;
    // clamp OOB rows to a valid row (results for those rows are never stored)
    const float* base0 = in + (size_t)(rb + min(r0, nrows - 1)) * K;
    const float* base1 = in + (size_t)(rb + min(r0 + 8, nrows - 1)) * K;

    float acc[8][4];
#pragma unroll
    for (int t = 0; t < 8; t++)
#pragma unroll
        for (int j = 0; j < 4; j++) acc[t][j] = 0.f;

    int c0 = 2 * qc;
    float2 p0 = __ldg((const float2*)(base0 + c0));
    float2 p1 = __ldg((const float2*)(base1 + c0));
    float2 p2 = __ldg((const float2*)(base0 + c0 + 8));
    float2 p3 = __ldg((const float2*)(base1 + c0 + 8));

#pragma unroll
    for (int kc = 0; kc < NKC; kc++) {
        float2 a0 = p0, a1 = p1, a2 = p2, a3 = p3;
        if (kc + 1 < NKC) {
            int cn = (kc + 1) * 16 + 2 * qc;
            p0 = __ldg((const float2*)(base0 + cn));
            p1 = __ldg((const float2*)(base1 + cn));
            p2 = __ldg((const float2*)(base0 + cn + 8));
            p3 = __ldg((const float2*)(base1 + cn + 8));
        }
        uint32_t ah[4], al[4];
        split2(a0.x, a0.y, ah[0], al[0]);
        split2(a1.x, a1.y, ah[1], al[1]);
        split2(a2.x, a2.y, ah[2], al[2]);
        split2(a3.x, a3.y, ah[3], al[3]);

        int bb = (kc * 8 + qc) * WST + qr;
#pragma unroll
        for (int t = 0; t < 8; t++) {
            uint32_t bh0 = Wh[bb + 8 * t];
            uint32_t bh1 = Wh[bb + 4 * WST + 8 * t];
            uint32_t bl0 = Wl[bb + 8 * t];
            uint32_t bl1 = Wl[bb + 4 * WST + 8 * t];
            MMA_BF16(acc[t], ah, bh0, bh1);
            MMA_BF16(acc[t], ah, bl0, bl1);
            MMA_BF16(acc[t], al, bh0, bh1);
        }
    }

    // direct global store: for fixed (t,qr), 4 qc-lanes fill one 32B sector
    bool ok0 = (r0 < nrows), ok1 = (r0 + 8 < nrows);
    float* o0 = out + (size_t)(rb + r0) * 64;
    float* o1 = out + (size_t)(rb + r0 + 8) * 64;
#pragma unroll
    for (int t = 0; t < 8; t++) {
        int c = 8 * t + qc * 2;
        if (ok0) *(float2*)(o0 + c) = make_float2(acc[t][0], acc[t][1]);
        if (ok1) *(float2*)(o1 + c) = make_float2(acc[t][2], acc[t][3]);
    }
}

// ---------------- sparse aggregation: warp per node, float2 per lane, 2-deep MLP ----------------
__global__ void aggregate_kernel(const float* __restrict__ t, const float* __restrict__ b,
                                 float* __restrict__ h, int n) {
    int i = blockIdx.x * blockDim.y + threadIdx.y;
    if (i >= n) return;
    int c2 = threadIdx.x;
    float2 bb = __ldg((const float2*)b + c2);
    float di = d_dinv[i];
    float2 v = __ldg((const float2*)(t + (size_t)i * HID) + c2);
    float ax = di * v.x, ay = di * v.y;
    int start = d_rowptr[i];
    int cnt = d_degE[i];
    int j = 0;
    for (; j + 2 <= cnt; j += 2) {
        int s0 = d_col[start + j], s1 = d_col[start + j + 1];
        float w0 = d_w[start + j], w1 = d_w[start + j + 1];
        float2 u0 = __ldg((const float2*)(t + (size_t)s0 * HID) + c2);
        float2 u1 = __ldg((const float2*)(t + (size_t)s1 * HID) + c2);
        ax += w0 * u0.x; ay += w0 * u0.y;
        ax += w1 * u1.x; ay += w1 * u1.y;
    }
    if (j < cnt) {
        int s = d_col[start + j];
        float w = d_w[start + j];
        float2 u = __ldg((const float2*)(t + (size_t)s * HID) + c2);
        ax += w * u.x; ay += w * u.y;
    }
    float2 o = make_float2(fmaxf(di * ax + bb.x, 0.f), fmaxf(di * ay + bb.y, 0.f));
    ((float2*)(h + (size_t)i * HID))[c2] = o;
}

// ---------------- pooling (sorted batch_index -> run-length local accum) ----------------
__global__ void pool_kernel(const float* __restrict__ h, const void* __restrict__ batch, int n) {
    int is64 = g_idx64;
    int c = threadIdx.x;  // 64
    int base = blockIdx.x * POOL_CHUNK;
    int end = min(base + POOL_CHUNK, n);
    int curg = -1, lc = 0;
    float ls = 0.f, lm = 0.f;
    for (int i = base; i < end; i++) {
        int g = ld_idx32(batch, i, is64);
        if (g != curg) {
            if (curg >= 0) {
                atomicAdd(&d_gsum[curg * HID + c], ls);
                atomicMax(&d_gmax[curg * HID + c], __float_as_uint(lm));
                if (c == 0) atomicAdd(&d_cnt[curg], lc);
            }
            curg = g; ls = 0.f; lm = 0.f; lc = 0;
        }
        float v = h[(size_t)i * HID + c];
        ls += v;
        lm = fmaxf(lm, v);
        lc++;
    }
    if (curg >= 0) {
        atomicAdd(&d_gsum[curg * HID + c], ls);
        atomicMax(&d_gmax[curg * HID + c], __float_as_uint(lm));
        if (c == 0) atomicAdd(&d_cnt[curg], lc);
    }
}

// ---------------- final ----------------
__global__ void final_kernel(const float* __restrict__ Wout, const float* __restrict__ bout,
                             float* __restrict__ out) {
    __shared__ float p[2 * HID];
    int g = blockIdx.x;
    int t = threadIdx.x;  // 128
    if (t < HID) {
        float cn = fmaxf((float)d_cnt[g], 1.f);
        p[t] = d_gsum[g * HID + t] / cn;
        p[HID + t] = __uint_as_float(d_gmax[g * HID + t]);
    }
    __syncthreads();
    if (t < NC) {
        float a = bout[t];
#pragma unroll 16
        for (int k = 0; k < 2 * HID; k++) a += p[k] * Wout[k * NC + t];
        out[g * NC + t] = a;
    }
}

// ---------------- launch ----------------
extern "C" void kernel_launch(void* const* d_in, const int* in_sizes, int n_in,
                              void* d_out, int out_size) {
    const float* x    = (const float*)d_in[0];
    const void*  ei   = d_in[1];
    const void*  bat  = d_in[2];
    const float* W0   = (const float*)d_in[3];
    const float* b0   = (const float*)d_in[4];
    const float* W1   = (const float*)d_in[5];
    const float* b1   = (const float*)d_in[6];
    const float* W2   = (const float*)d_in[7];
    const float* b2   = (const float*)d_in[8];
    const float* Wout = (const float*)d_in[9];
    const float* bout = (const float*)d_in[10];
    float* out = (float*)d_out;

    int N = in_sizes[2];
    int E = in_sizes[1] / 2;

    float *hp, *tp;
    cudaGetSymbolAddress((void**)&hp, d_hbuf);
    cudaGetSymbolAddress((void**)&tp, d_tbuf);

    int gblk = (N + 127) / 128;
    dim3 aggB(32, 8);
    int aggG = (N + 7) / 8;

    detect_kernel<<<1, 256>>>((const unsigned*)ei);
    zero_kernel<<<(N + 255) / 256, 256>>>(N);
    hist_kernel<<<(E + 255) / 256, 256>>>(ei, E);
    gemm_mma<128><<<gblk, 256>>>(x, W0, tp, N);   // 4th launch -> profiled slot
    dinv_kernel<<<(N + 255) / 256, 256>>>(N);

    int nb = (N + SCAN_B - 1) / SCAN_B;
    scanA_kernel<<<nb, SCAN_T>>>(N);
    scanB_kernel<<<1, 512>>>(nb);
    scanC_kernel<<<(N + 255) / 256, 256>>>(N);
    scatter_kernel<<<(E + 255) / 256, 256>>>(ei, E);

    aggregate_kernel<<<aggG, aggB>>>(tp, b0, hp, N);
    gemm_mma<64><<<gblk, 256>>>(hp, W1, tp, N);
    aggregate_kernel<<<aggG, aggB>>>(tp, b1, hp, N);
    gemm_mma<64><<<gblk, 256>>>(hp, W2, tp, N);
    aggregate_kernel<<<aggG, aggB>>>(tp, b2, hp, N);

    pool_kernel<<<(N + POOL_CHUNK - 1) / POOL_CHUNK, 64>>>(hp, bat, N);
    final_kernel<<<NG, 128>>>(Wout, bout, out);
}

// round 6
// speedup vs baseline: 1.8123x; 1.0047x over previous
#include <cuda_runtime.h>
#include <cuda_bf16.h>
#include <cstdint>

#define NN 500000
#define NE 1250000
#define HID 64
#define NG 512
#define NC 10

#define SCAN_T 256
#define SCAN_I 4
#define SCAN_B (SCAN_T*SCAN_I)   // 1024

// ---------------- device scratch ----------------
__device__ int      g_idx64;
__device__ int      d_degE[NN];
__device__ float    d_dinv[NN];
__device__ int      d_rowptr[NN];
__device__ int      d_cursor[NN];
__device__ int      d_bsums[512];
__device__ int      d_col[NE];
__device__ float    d_w[NE];
__device__ float    d_hbuf[(size_t)NN*HID];
__device__ float    d_tbuf[(size_t)NN*HID];
__device__ float    d_gsum[NG*HID];
__device__ unsigned d_gmax[NG*HID];
__device__ int      d_cnt[NG];

__device__ __forceinline__ int ld_idx32(const void* p, long long j, int is64) {
    const unsigned* u = (const unsigned*)p;
    return (int)(is64 ? u[2*j] : u[j]);
}

// ---------------- index-width detection ----------------
__global__ void detect_kernel(const unsigned* __restrict__ p) {
    __shared__ unsigned red[256];
    int t = threadIdx.x;
    unsigned v = 0;
    for (int i = 2 * t + 1; i < 4096; i += 512) v |= p[i];
    red[t] = v;
    __syncthreads();
    for (int off = 128; off > 0; off >>= 1) {
        if (t < off) red[t] |= red[t + off];
        __syncthreads();
    }
    if (t == 0) g_idx64 = (red[0] == 0) ? 1 : 0;
}

__global__ void zero_kernel(int n) {
    int i = blockIdx.x * blockDim.x + threadIdx.x;
    if (i < n) d_degE[i] = 0;
    if (i < NG * HID) { d_gsum[i] = 0.f; d_gmax[i] = 0u; }
    if (i < NG) d_cnt[i] = 0;
}

__global__ void hist_kernel(const void* __restrict__ ei, int E) {
    int e = blockIdx.x * blockDim.x + threadIdx.x;
    if (e >= E) return;
    int dd = ld_idx32(ei, (long long)E + e, g_idx64);
    atomicAdd(&d_degE[dd], 1);
}

__global__ void dinv_kernel(int n) {
    int i = blockIdx.x * blockDim.x + threadIdx.x;
    if (i < n) d_dinv[i] = rsqrtf((float)d_degE[i] + 1.0f);
}

// ---------------- exclusive scan ----------------
__global__ void scanA_kernel(int n) {
    __shared__ int sm[SCAN_T];
    int b = blockIdx.x, t = threadIdx.x;
    int base = b * SCAN_B + t * SCAN_I;
    int v[SCAN_I];
    int s = 0;
#pragma unroll
    for (int j = 0; j < SCAN_I; j++) {
        v[j] = (base + j < n) ? d_degE[base + j] : 0;
        s += v[j];
    }
    sm[t] = s;
    __syncthreads();
    for (int off = 1; off < SCAN_T; off <<= 1) {
        int x = (t >= off) ? sm[t - off] : 0;
        __syncthreads();
        sm[t] += x;
        __syncthreads();
    }
    int excl = (t > 0) ? sm[t - 1] : 0;
    if (t == SCAN_T - 1) d_bsums[b] = sm[t];
    int run = excl;
#pragma unroll
    for (int j = 0; j < SCAN_I; j++) {
        if (base + j < n) d_rowptr[base + j] = run;
        run += v[j];
    }
}

__global__ void scanB_kernel(int nb) {
    __shared__ int sm[512];
    int t = threadIdx.x;
    sm[t] = (t < nb) ? d_bsums[t] : 0;
    __syncthreads();
    for (int off = 1; off < 512; off <<= 1) {
        int x = (t >= off) ? sm[t - off] : 0;
        __syncthreads();
        sm[t] += x;
        __syncthreads();
    }
    int excl = (t > 0) ? sm[t - 1] : 0;
    if (t < nb) d_bsums[t] = excl;
}

__global__ void scanC_kernel(int n) {
    int i = blockIdx.x * blockDim.x + threadIdx.x;
    if (i < n) {
        int v = d_rowptr[i] + d_bsums[i / SCAN_B];
        d_rowptr[i] = v;
        d_cursor[i] = v;
    }
}

__global__ void scatter_kernel(const void* __restrict__ ei, int E) {
    int e = blockIdx.x * blockDim.x + threadIdx.x;
    if (e >= E) return;
    int is64 = g_idx64;
    int ss = ld_idx32(ei, e, is64);
    int dd = ld_idx32(ei, (long long)E + e, is64);
    int pos = atomicAdd(&d_cursor[dd], 1);
    d_col[pos] = ss;
    d_w[pos] = d_dinv[ss];
}

// ---------------- fast bf16x2 split ----------------
__device__ __forceinline__ void split2(float v0, float v1, uint32_t& hi, uint32_t& lo) {
    uint32_t h;
    asm("cvt.rn.bf16x2.f32 %0, %1, %2;" : "=r"(h) : "f"(v1), "f"(v0));
    float f0 = __uint_as_float(h << 16);
    float f1 = __uint_as_float(h & 0xFFFF0000u);
    asm("cvt.rn.bf16x2.f32 %0, %1, %2;" : "=r"(lo) : "f"(v1 - f1), "f"(v0 - f0));
    hi = h;
}

#define MMA_BF16(c, a, b0v, b1v) \
    asm volatile("mma.sync.aligned.m16n8k16.row.col.f32.bf16.bf16.f32 " \
        "{%0,%1,%2,%3}, {%4,%5,%6,%7}, {%8,%9}, {%0,%1,%2,%3};" \
        : "+f"((c)[0]), "+f"((c)[1]), "+f"((c)[2]), "+f"((c)[3]) \
        : "r"((a)[0]), "r"((a)[1]), "r"((a)[2]), "r"((a)[3]), "r"(b0v), "r"(b1v))

// ---------------- layer-0 GEMM: out[N,64] = in[N,128] @ W[128,64] ----------------
// A loaded direct from gmem as float4 (k-permuted: lane qc holds k-pairs 2qc, 2qc+1;
// W packing permuted to match). Distance-2 prefetch. D = Ahi*Whi + Ahi*Wlo + Alo*Whi.
__global__ void __launch_bounds__(256, 2) gemm_mma128(const float* __restrict__ in,
                                                      const float* __restrict__ W,
                                                      float* __restrict__ out, int n) {
    constexpr int K = 128, K2 = 64, WST = 72, NKC = 8;
    __shared__ uint32_t Wh[K2 * WST];
    __shared__ uint32_t Wl[K2 * WST];

    int tid = threadIdx.x, wid = tid >> 5, lane = tid & 31;
    int rb = blockIdx.x * 128;
    int nrows = min(128, n - rb);

    // pack W with chunk-local permutation: position m<4 -> orig pair 2m; m>=4 -> 2(m-4)+1
    for (int i = tid; i < K2 * 64; i += 256) {
        int p = i >> 6, nn = i & 63;
        int chunk = p >> 3, m = p & 7;
        int o = (chunk << 3) + ((m < 4) ? 2 * m : 2 * (m - 4) + 1);
        uint32_t hi, lo;
        split2(W[(2 * o) * 64 + nn], W[(2 * o + 1) * 64 + nn], hi, lo);
        Wh[p * WST + nn] = hi;
        Wl[p * WST + nn] = lo;
    }
    __syncthreads();

    int qr = lane >> 2, qc = lane & 3;
    int r0 = wid * 16 + qr;
    const float* base0 = in + (size_t)(rb + min(r0, nrows - 1)) * K;
    const float* base1 = in + (size_t)(rb + min(r0 + 8, nrows - 1)) * K;

    float acc[8][4];
#pragma unroll
    for (int t = 0; t < 8; t++)
#pragma unroll
        for (int j = 0; j < 4; j++) acc[t][j] = 0.f;

    float4 pf[2][2];
    pf[0][0] = __ldg((const float4*)(base0 + 4 * qc));
    pf[0][1] = __ldg((const float4*)(base1 + 4 * qc));
    pf[1][0] = __ldg((const float4*)(base0 + 16 + 4 * qc));
    pf[1][1] = __ldg((const float4*)(base1 + 16 + 4 * qc));

#pragma unroll
    for (int kc = 0; kc < NKC; kc++) {
        float4 a0 = pf[kc & 1][0], a1 = pf[kc & 1][1];
        if (kc + 2 < NKC) {
            int cn = (kc + 2) * 16 + 4 * qc;
            pf[kc & 1][0] = __ldg((const float4*)(base0 + cn));
            pf[kc & 1][1] = __ldg((const float4*)(base1 + cn));
        }
        uint32_t ah[4], al[4];
        split2(a0.x, a0.y, ah[0], al[0]);   // row r0,   pair 2qc   -> slot a0
        split2(a1.x, a1.y, ah[1], al[1]);   // row r0+8, pair 2qc   -> slot a1
        split2(a0.z, a0.w, ah[2], al[2]);   // row r0,   pair 2qc+1 -> slot a2
        split2(a1.z, a1.w, ah[3], al[3]);   // row r0+8, pair 2qc+1 -> slot a3

        int bb = (kc * 8 + qc) * WST + qr;
#pragma unroll
        for (int t = 0; t < 8; t++) {
            uint32_t bh0 = Wh[bb + 8 * t];
            uint32_t bh1 = Wh[bb + 4 * WST + 8 * t];
            uint32_t bl0 = Wl[bb + 8 * t];
            uint32_t bl1 = Wl[bb + 4 * WST + 8 * t];
            MMA_BF16(acc[t], ah, bh0, bh1);
            MMA_BF16(acc[t], ah, bl0, bl1);
            MMA_BF16(acc[t], al, bh0, bh1);
        }
    }

    bool ok0 = (r0 < nrows), ok1 = (r0 + 8 < nrows);
    float* o0 = out + (size_t)(rb + r0) * 64;
    float* o1 = out + (size_t)(rb + r0 + 8) * 64;
#pragma unroll
    for (int t = 0; t < 8; t++) {
        int c = 8 * t + qc * 2;
        if (ok0) *(float2*)(o0 + c) = make_float2(acc[t][0], acc[t][1]);
        if (ok1) *(float2*)(o1 + c) = make_float2(acc[t][2], acc[t][3]);
    }
}

// ---------------- aggregate one node's float2 (channels 2c2, 2c2+1) ----------------
__device__ __forceinline__ float2 agg_node(const float* __restrict__ t, int i, int c2, float2 bb) {
    float di = d_dinv[i];
    float2 v = __ldg((const float2*)(t + (size_t)i * HID) + c2);
    float ax = di * v.x, ay = di * v.y;
    int start = d_rowptr[i];
    int cnt = d_degE[i];
    int j = 0;
    for (; j + 2 <= cnt; j += 2) {
        int s0 = d_col[start + j], s1 = d_col[start + j + 1];
        float w0 = d_w[start + j], w1 = d_w[start + j + 1];
        float2 u0 = __ldg((const float2*)(t + (size_t)s0 * HID) + c2);
        float2 u1 = __ldg((const float2*)(t + (size_t)s1 * HID) + c2);
        ax += w0 * u0.x; ay += w0 * u0.y;
        ax += w1 * u1.x; ay += w1 * u1.y;
    }
    if (j < cnt) {
        int s = d_col[start + j];
        float w = d_w[start + j];
        float2 u = __ldg((const float2*)(t + (size_t)s * HID) + c2);
        ax += w * u.x; ay += w * u.y;
    }
    return make_float2(fmaxf(di * ax + bb.x, 0.f), fmaxf(di * ay + bb.y, 0.f));
}

// ---------------- fused aggregate + GEMM64: out = relu(agg(t)+bias) @ W ----------------
// CTA = 128 nodes, 256 threads / 8 warps. Phase 1: warp w aggregates nodes 16w..16w+15
// into smem hi/lo A tiles. Phase 2: HMMA from smem (K=64).
__global__ void __launch_bounds__(256, 2) fused_agg_gemm(const float* __restrict__ t,
                                                         const float* __restrict__ bias,
                                                         const float* __restrict__ W,
                                                         float* __restrict__ out, int n) {
    constexpr int AST = 36, WST = 72, NKC = 4;
    extern __shared__ uint32_t sm[];
    uint32_t* Ah = sm;                   // [128][36]
    uint32_t* Al = Ah + 128 * AST;
    uint32_t* Wh = Al + 128 * AST;       // [32][72]
    uint32_t* Wl = Wh + 32 * WST;

    int tid = threadIdx.x, wid = tid >> 5, lane = tid & 31;
    int rb = blockIdx.x * 128;
    int nrows = min(128, n - rb);

    // pack W (natural pair order)
    for (int i = tid; i < 32 * 64; i += 256) {
        int k2 = i >> 6, nn = i & 63;
        uint32_t hi, lo;
        split2(W[(2 * k2) * 64 + nn], W[(2 * k2 + 1) * 64 + nn], hi, lo);
        Wh[k2 * WST + nn] = hi;
        Wl[k2 * WST + nn] = lo;
    }

    // phase 1: aggregate 16 nodes per warp into smem
    {
        int c2 = lane;
        float2 bb = __ldg((const float2*)bias + c2);
#pragma unroll 1
        for (int j = 0; j < 16; j++) {
            int r = wid * 16 + j;
            float2 h = make_float2(0.f, 0.f);
            if (r < nrows) h = agg_node(t, rb + r, c2, bb);
            uint32_t hi, lo;
            split2(h.x, h.y, hi, lo);
            Ah[r * AST + c2] = hi;
            Al[r * AST + c2] = lo;
        }
    }
    __syncthreads();

    // phase 2: MMA from smem
    int qr = lane >> 2, qc = lane & 3;
    int r0 = wid * 16 + qr;
    float acc[8][4];
#pragma unroll
    for (int t8 = 0; t8 < 8; t8++)
#pragma unroll
        for (int j = 0; j < 4; j++) acc[t8][j] = 0.f;

#pragma unroll
    for (int kc = 0; kc < NKC; kc++) {
        int ab = r0 * AST + kc * 8 + qc;
        uint32_t ah[4], al[4];
        ah[0] = Ah[ab];         ah[1] = Ah[ab + 8 * AST];
        ah[2] = Ah[ab + 4];     ah[3] = Ah[ab + 8 * AST + 4];
        al[0] = Al[ab];         al[1] = Al[ab + 8 * AST];
        al[2] = Al[ab + 4];     al[3] = Al[ab + 8 * AST + 4];
        int bb2 = (kc * 8 + qc) * WST + qr;
#pragma unroll
        for (int t8 = 0; t8 < 8; t8++) {
            uint32_t bh0 = Wh[bb2 + 8 * t8];
            uint32_t bh1 = Wh[bb2 + 4 * WST + 8 * t8];
            uint32_t bl0 = Wl[bb2 + 8 * t8];
            uint32_t bl1 = Wl[bb2 + 4 * WST + 8 * t8];
            MMA_BF16(acc[t8], ah, bh0, bh1);
            MMA_BF16(acc[t8], ah, bl0, bl1);
            MMA_BF16(acc[t8], al, bh0, bh1);
        }
    }

    bool ok0 = (r0 < nrows), ok1 = (r0 + 8 < nrows);
    float* o0 = out + (size_t)(rb + r0) * 64;
    float* o1 = out + (size_t)(rb + r0 + 8) * 64;
#pragma unroll
    for (int t8 = 0; t8 < 8; t8++) {
        int c = 8 * t8 + qc * 2;
        if (ok0) *(float2*)(o0 + c) = make_float2(acc[t8][0], acc[t8][1]);
        if (ok1) *(float2*)(o1 + c) = make_float2(acc[t8][2], acc[t8][3]);
    }
}

// ---------------- fused aggregate + pool: h never hits DRAM ----------------
// Warp handles 16 consecutive nodes; run-length accumulate into gsum/gmax/cnt.
__global__ void fused_agg_pool(const float* __restrict__ t, const float* __restrict__ bias,
                               const void* __restrict__ batch, int n) {
    int tid = threadIdx.x, wid = tid >> 5, lane = tid & 31;
    int is64 = g_idx64;
    int c2 = lane;
    float2 bb = __ldg((const float2*)bias + c2);
    int base = blockIdx.x * 128 + wid * 16;

    int curg = -1, lc = 0;
    float lsx = 0.f, lsy = 0.f, lmx = 0.f, lmy = 0.f;
#pragma unroll 1
    for (int j = 0; j < 16; j++) {
        int i = base + j;
        if (i >= n) break;
        int g = ld_idx32(batch, i, is64);
        if (g != curg) {
            if (curg >= 0) {
                atomicAdd(&d_gsum[curg * HID + 2 * c2], lsx);
                atomicAdd(&d_gsum[curg * HID + 2 * c2 + 1], lsy);
                atomicMax(&d_gmax[curg * HID + 2 * c2], __float_as_uint(lmx));
                atomicMax(&d_gmax[curg * HID + 2 * c2 + 1], __float_as_uint(lmy));
                if (lane == 0) atomicAdd(&d_cnt[curg], lc);
            }
            curg = g; lsx = lsy = lmx = lmy = 0.f; lc = 0;
        }
        float2 h = agg_node(t, i, c2, bb);
        lsx += h.x; lsy += h.y;
        lmx = fmaxf(lmx, h.x); lmy = fmaxf(lmy, h.y);
        lc++;
    }
    if (curg >= 0) {
        atomicAdd(&d_gsum[curg * HID + 2 * c2], lsx);
        atomicAdd(&d_gsum[curg * HID + 2 * c2 + 1], lsy);
        atomicMax(&d_gmax[curg * HID + 2 * c2], __float_as_uint(lmx));
        atomicMax(&d_gmax[curg * HID + 2 * c2 + 1], __float_as_uint(lmy));
        if (lane == 0) atomicAdd(&d_cnt[curg], lc);
    }
}

// ---------------- final ----------------
__global__ void final_kernel(const float* __restrict__ Wout, const float* __restrict__ bout,
                             float* __restrict__ out) {
    __shared__ float p[2 * HID];
    int g = blockIdx.x;
    int t = threadIdx.x;  // 128
    if (t < HID) {
        float cn = fmaxf((float)d_cnt[g], 1.f);
        p[t] = d_gsum[g * HID + t] / cn;
        p[HID + t] = __uint_as_float(d_gmax[g * HID + t]);
    }
    __syncthreads();
    if (t < NC) {
        float a = bout[t];
#pragma unroll 16
        for (int k = 0; k < 2 * HID; k++) a += p[k] * Wout[k * NC + t];
        out[g * NC + t] = a;
    }
}

// ---------------- launch ----------------
extern "C" void kernel_launch(void* const* d_in, const int* in_sizes, int n_in,
                              void* d_out, int out_size) {
    const float* x    = (const float*)d_in[0];
    const void*  ei   = d_in[1];
    const void*  bat  = d_in[2];
    const float* W0   = (const float*)d_in[3];
    const float* b0   = (const float*)d_in[4];
    const float* W1   = (const float*)d_in[5];
    const float* b1   = (const float*)d_in[6];
    const float* W2   = (const float*)d_in[7];
    const float* b2   = (const float*)d_in[8];
    const float* Wout = (const float*)d_in[9];
    const float* bout = (const float*)d_in[10];
    float* out = (float*)d_out;

    int N = in_sizes[2];
    int E = in_sizes[1] / 2;

    float *hp, *tp;
    cudaGetSymbolAddress((void**)&hp, d_hbuf);
    cudaGetSymbolAddress((void**)&tp, d_tbuf);

    int fsmem = (2 * 128 * 36 + 2 * 32 * 72) * 4;  // 55296
    cudaFuncSetAttribute(fused_agg_gemm, cudaFuncAttributeMaxDynamicSharedMemorySize, fsmem);

    int gblk = (N + 127) / 128;

    detect_kernel<<<1, 256>>>((const unsigned*)ei);
    zero_kernel<<<(N + 255) / 256, 256>>>(N);
    hist_kernel<<<(E + 255) / 256, 256>>>(ei, E);
    gemm_mma128<<<gblk, 256>>>(x, W0, tp, N);   // 4th launch -> profiled slot
    dinv_kernel<<<(N + 255) / 256, 256>>>(N);

    int nb = (N + SCAN_B - 1) / SCAN_B;
    scanA_kernel<<<nb, SCAN_T>>>(N);
    scanB_kernel<<<1, 512>>>(nb);
    scanC_kernel<<<(N + 255) / 256, 256>>>(N);
    scatter_kernel<<<(E + 255) / 256, 256>>>(ei, E);

    fused_agg_gemm<<<gblk, 256, fsmem>>>(tp, b0, W1, hp, N);
    fused_agg_gemm<<<gblk, 256, fsmem>>>(hp, b1, W2, tp, N);
    fused_agg_pool<<<gblk, 256>>>(tp, b2, bat, N);
    final_kernel<<<NG, 128>>>(Wout, bout, out);
}

// round 7
// speedup vs baseline: 2.0183x; 1.1136x over previous
#include <cuda_runtime.h>
#include <cuda_bf16.h>
#include <cstdint>

#define NN 500000
#define NE 1250000
#define HID 64
#define NG 512
#define NC 10

#define SCAN_T 256
#define SCAN_I 4
#define SCAN_B (SCAN_T*SCAN_I)   // 1024

// ---------------- device scratch ----------------
__device__ int      g_idx64;
__device__ int      d_degE[NN];
__device__ float    d_dinv[NN];
__device__ int      d_rowptr[NN];
__device__ int      d_cursor[NN];
__device__ int      d_bsums[512];
__device__ int      d_col[NE];
__device__ float    d_w[NE];
__device__ float    d_hbuf[(size_t)NN*HID];
__device__ float    d_tbuf[(size_t)NN*HID];
__device__ float    d_gsum[NG*HID];
__device__ unsigned d_gmax[NG*HID];
__device__ int      d_cnt[NG];

__device__ __forceinline__ int ld_idx32(const void* p, long long j, int is64) {
    const unsigned* u = (const unsigned*)p;
    return (int)(is64 ? u[2*j] : u[j]);
}

// ---------------- index-width detection ----------------
__global__ void detect_kernel(const unsigned* __restrict__ p) {
    __shared__ unsigned red[256];
    int t = threadIdx.x;
    unsigned v = 0;
    for (int i = 2 * t + 1; i < 4096; i += 512) v |= p[i];
    red[t] = v;
    __syncthreads();
    for (int off = 128; off > 0; off >>= 1) {
        if (t < off) red[t] |= red[t + off];
        __syncthreads();
    }
    if (t == 0) g_idx64 = (red[0] == 0) ? 1 : 0;
}

__global__ void zero_kernel(int n) {
    int i = blockIdx.x * blockDim.x + threadIdx.x;
    if (i < n) d_degE[i] = 0;
    if (i < NG * HID) { d_gsum[i] = 0.f; d_gmax[i] = 0u; }
    if (i < NG) d_cnt[i] = 0;
}

__global__ void hist_kernel(const void* __restrict__ ei, int E) {
    int e = blockIdx.x * blockDim.x + threadIdx.x;
    if (e >= E) return;
    int dd = ld_idx32(ei, (long long)E + e, g_idx64);
    atomicAdd(&d_degE[dd], 1);
}

__global__ void dinv_kernel(int n) {
    int i = blockIdx.x * blockDim.x + threadIdx.x;
    if (i < n) d_dinv[i] = rsqrtf((float)d_degE[i] + 1.0f);
}

// ---------------- exclusive scan ----------------
__global__ void scanA_kernel(int n) {
    __shared__ int sm[SCAN_T];
    int b = blockIdx.x, t = threadIdx.x;
    int base = b * SCAN_B + t * SCAN_I;
    int v[SCAN_I];
    int s = 0;
#pragma unroll
    for (int j = 0; j < SCAN_I; j++) {
        v[j] = (base + j < n) ? d_degE[base + j] : 0;
        s += v[j];
    }
    sm[t] = s;
    __syncthreads();
    for (int off = 1; off < SCAN_T; off <<= 1) {
        int x = (t >= off) ? sm[t - off] : 0;
        __syncthreads();
        sm[t] += x;
        __syncthreads();
    }
    int excl = (t > 0) ? sm[t - 1] : 0;
    if (t == SCAN_T - 1) d_bsums[b] = sm[t];
    int run = excl;
#pragma unroll
    for (int j = 0; j < SCAN_I; j++) {
        if (base + j < n) d_rowptr[base + j] = run;
        run += v[j];
    }
}

__global__ void scanB_kernel(int nb) {
    __shared__ int sm[512];
    int t = threadIdx.x;
    sm[t] = (t < nb) ? d_bsums[t] : 0;
    __syncthreads();
    for (int off = 1; off < 512; off <<= 1) {
        int x = (t >= off) ? sm[t - off] : 0;
        __syncthreads();
        sm[t] += x;
        __syncthreads();
    }
    int excl = (t > 0) ? sm[t - 1] : 0;
    if (t < nb) d_bsums[t] = excl;
}

__global__ void scanC_kernel(int n) {
    int i = blockIdx.x * blockDim.x + threadIdx.x;
    if (i < n) {
        int v = d_rowptr[i] + d_bsums[i / SCAN_B];
        d_rowptr[i] = v;
        d_cursor[i] = v;
    }
}

__global__ void scatter_kernel(const void* __restrict__ ei, int E) {
    int e = blockIdx.x * blockDim.x + threadIdx.x;
    if (e >= E) return;
    int is64 = g_idx64;
    int ss = ld_idx32(ei, e, is64);
    int dd = ld_idx32(ei, (long long)E + e, is64);
    int pos = atomicAdd(&d_cursor[dd], 1);
    d_col[pos] = ss;
    d_w[pos] = d_dinv[ss];
}

// ---------------- fast bf16x2 split ----------------
__device__ __forceinline__ void split2(float v0, float v1, uint32_t& hi, uint32_t& lo) {
    uint32_t h;
    asm("cvt.rn.bf16x2.f32 %0, %1, %2;" : "=r"(h) : "f"(v1), "f"(v0));
    float f0 = __uint_as_float(h << 16);
    float f1 = __uint_as_float(h & 0xFFFF0000u);
    asm("cvt.rn.bf16x2.f32 %0, %1, %2;" : "=r"(lo) : "f"(v1 - f1), "f"(v0 - f0));
    hi = h;
}

#define MMA_BF16(c, a, b0v, b1v) \
    asm volatile("mma.sync.aligned.m16n8k16.row.col.f32.bf16.bf16.f32 " \
        "{%0,%1,%2,%3}, {%4,%5,%6,%7}, {%8,%9}, {%0,%1,%2,%3};" \
        : "+f"((c)[0]), "+f"((c)[1]), "+f"((c)[2]), "+f"((c)[3]) \
        : "r"((a)[0]), "r"((a)[1]), "r"((a)[2]), "r"((a)[3]), "r"(b0v), "r"(b1v))

// ---------------- layer-0 GEMM: out[N,64] = in[N,128] @ W[128,64] ----------------
__global__ void __launch_bounds__(256, 2) gemm_mma128(const float* __restrict__ in,
                                                      const float* __restrict__ W,
                                                      float* __restrict__ out, int n) {
    constexpr int K = 128, K2 = 64, WST = 72, NKC = 8;
    __shared__ uint32_t Wh[K2 * WST];
    __shared__ uint32_t Wl[K2 * WST];

    int tid = threadIdx.x, wid = tid >> 5, lane = tid & 31;
    int rb = blockIdx.x * 128;
    int nrows = min(128, n - rb);

    for (int i = tid; i < K2 * 64; i += 256) {
        int p = i >> 6, nn = i & 63;
        int chunk = p >> 3, m = p & 7;
        int o = (chunk << 3) + ((m < 4) ? 2 * m : 2 * (m - 4) + 1);
        uint32_t hi, lo;
        split2(W[(2 * o) * 64 + nn], W[(2 * o + 1) * 64 + nn], hi, lo);
        Wh[p * WST + nn] = hi;
        Wl[p * WST + nn] = lo;
    }
    __syncthreads();

    int qr = lane >> 2, qc = lane & 3;
    int r0 = wid * 16 + qr;
    const float* base0 = in + (size_t)(rb + min(r0, nrows - 1)) * K;
    const float* base1 = in + (size_t)(rb + min(r0 + 8, nrows - 1)) * K;

    float acc[8][4];
#pragma unroll
    for (int t = 0; t < 8; t++)
#pragma unroll
        for (int j = 0; j < 4; j++) acc[t][j] = 0.f;

    float4 pf[2][2];
    pf[0][0] = __ldg((const float4*)(base0 + 4 * qc));
    pf[0][1] = __ldg((const float4*)(base1 + 4 * qc));
    pf[1][0] = __ldg((const float4*)(base0 + 16 + 4 * qc));
    pf[1][1] = __ldg((const float4*)(base1 + 16 + 4 * qc));

#pragma unroll
    for (int kc = 0; kc < NKC; kc++) {
        float4 a0 = pf[kc & 1][0], a1 = pf[kc & 1][1];
        if (kc + 2 < NKC) {
            int cn = (kc + 2) * 16 + 4 * qc;
            pf[kc & 1][0] = __ldg((const float4*)(base0 + cn));
            pf[kc & 1][1] = __ldg((const float4*)(base1 + cn));
        }
        uint32_t ah[4], al[4];
        split2(a0.x, a0.y, ah[0], al[0]);
        split2(a1.x, a1.y, ah[1], al[1]);
        split2(a0.z, a0.w, ah[2], al[2]);
        split2(a1.z, a1.w, ah[3], al[3]);

        int bb = (kc * 8 + qc) * WST + qr;
#pragma unroll
        for (int t = 0; t < 8; t++) {
            uint32_t bh0 = Wh[bb + 8 * t];
            uint32_t bh1 = Wh[bb + 4 * WST + 8 * t];
            uint32_t bl0 = Wl[bb + 8 * t];
            uint32_t bl1 = Wl[bb + 4 * WST + 8 * t];
            MMA_BF16(acc[t], ah, bh0, bh1);
            MMA_BF16(acc[t], ah, bl0, bl1);
            MMA_BF16(acc[t], al, bh0, bh1);
        }
    }

    bool ok0 = (r0 < nrows), ok1 = (r0 + 8 < nrows);
    float* o0 = out + (size_t)(rb + r0) * 64;
    float* o1 = out + (size_t)(rb + r0 + 8) * 64;
#pragma unroll
    for (int t = 0; t < 8; t++) {
        int c = 8 * t + qc * 2;
        if (ok0) *(float2*)(o0 + c) = make_float2(acc[t][0], acc[t][1]);
        if (ok1) *(float2*)(o1 + c) = make_float2(acc[t][2], acc[t][3]);
    }
}

// ---------------- single-node aggregate (tail path) ----------------
__device__ __forceinline__ float2 agg_node(const float* __restrict__ t, int i, int c2, float2 bb) {
    float di = d_dinv[i];
    const float2* t2 = (const float2*)t;
    float2 v = __ldg(t2 + (size_t)i * 32 + c2);
    float ax = di * v.x, ay = di * v.y;
    int start = d_rowptr[i];
    int cnt = d_degE[i];
    int j = 0;
    for (; j + 2 <= cnt; j += 2) {
        int s0 = d_col[start + j], s1 = d_col[start + j + 1];
        float w0 = d_w[start + j], w1 = d_w[start + j + 1];
        float2 u0 = __ldg(t2 + (size_t)s0 * 32 + c2);
        float2 u1 = __ldg(t2 + (size_t)s1 * 32 + c2);
        ax += w0 * u0.x; ay += w0 * u0.y;
        ax += w1 * u1.x; ay += w1 * u1.y;
    }
    if (j < cnt) {
        int s = d_col[start + j];
        float w = d_w[start + j];
        float2 u = __ldg(t2 + (size_t)s * 32 + c2);
        ax += w * u.x; ay += w * u.y;
    }
    return make_float2(fmaxf(di * ax + bb.x, 0.f), fmaxf(di * ay + bb.y, 0.f));
}

// ---------------- paired aggregate: two nodes, interleaved gathers (MLP 4) ----------------
__device__ __forceinline__ void agg_pair(const float* __restrict__ t, int i0, int i1,
                                         int c2, float2 bb, float2& h0, float2& h1) {
    const float2* t2 = (const float2*)t;
    float d0 = d_dinv[i0], d1 = d_dinv[i1];
    float2 v0 = __ldg(t2 + (size_t)i0 * 32 + c2);
    float2 v1 = __ldg(t2 + (size_t)i1 * 32 + c2);
    float ax0 = d0 * v0.x, ay0 = d0 * v0.y;
    float ax1 = d1 * v1.x, ay1 = d1 * v1.y;
    int r0 = d_rowptr[i0], n0 = d_degE[i0];
    int r1 = d_rowptr[i1], n1 = d_degE[i1];
    int m = min(n0, n1);
    int j = 0;
    for (; j + 2 <= m; j += 2) {
        int sa = d_col[r0 + j], sb = d_col[r0 + j + 1];
        int sc = d_col[r1 + j], sd = d_col[r1 + j + 1];
        float wa = d_w[r0 + j], wb = d_w[r0 + j + 1];
        float wc = d_w[r1 + j], wd = d_w[r1 + j + 1];
        float2 ua = __ldg(t2 + (size_t)sa * 32 + c2);
        float2 ub = __ldg(t2 + (size_t)sb * 32 + c2);
        float2 uc = __ldg(t2 + (size_t)sc * 32 + c2);
        float2 ud = __ldg(t2 + (size_t)sd * 32 + c2);
        ax0 += wa * ua.x; ay0 += wa * ua.y;
        ax1 += wc * uc.x; ay1 += wc * uc.y;
        ax0 += wb * ub.x; ay0 += wb * ub.y;
        ax1 += wd * ud.x; ay1 += wd * ud.y;
    }
    if (j < m) {
        int sa = d_col[r0 + j], sc = d_col[r1 + j];
        float wa = d_w[r0 + j], wc = d_w[r1 + j];
        float2 ua = __ldg(t2 + (size_t)sa * 32 + c2);
        float2 uc = __ldg(t2 + (size_t)sc * 32 + c2);
        ax0 += wa * ua.x; ay0 += wa * ua.y;
        ax1 += wc * uc.x; ay1 += wc * uc.y;
        j++;
    }
    int ja = j;
    for (; ja + 2 <= n0; ja += 2) {
        int sa = d_col[r0 + ja], sb = d_col[r0 + ja + 1];
        float wa = d_w[r0 + ja], wb = d_w[r0 + ja + 1];
        float2 ua = __ldg(t2 + (size_t)sa * 32 + c2);
        float2 ub = __ldg(t2 + (size_t)sb * 32 + c2);
        ax0 += wa * ua.x; ay0 += wa * ua.y;
        ax0 += wb * ub.x; ay0 += wb * ub.y;
    }
    if (ja < n0) {
        int sa = d_col[r0 + ja];
        float wa = d_w[r0 + ja];
        float2 ua = __ldg(t2 + (size_t)sa * 32 + c2);
        ax0 += wa * ua.x; ay0 += wa * ua.y;
    }
    int jb = j;
    for (; jb + 2 <= n1; jb += 2) {
        int sc = d_col[r1 + jb], sd = d_col[r1 + jb + 1];
        float wc = d_w[r1 + jb], wd = d_w[r1 + jb + 1];
        float2 uc = __ldg(t2 + (size_t)sc * 32 + c2);
        float2 ud = __ldg(t2 + (size_t)sd * 32 + c2);
        ax1 += wc * uc.x; ay1 += wc * uc.y;
        ax1 += wd * ud.x; ay1 += wd * ud.y;
    }
    if (jb < n1) {
        int sc = d_col[r1 + jb];
        float wc = d_w[r1 + jb];
        float2 uc = __ldg(t2 + (size_t)sc * 32 + c2);
        ax1 += wc * uc.x; ay1 += wc * uc.y;
    }
    h0 = make_float2(fmaxf(d0 * ax0 + bb.x, 0.f), fmaxf(d0 * ay0 + bb.y, 0.f));
    h1 = make_float2(fmaxf(d1 * ax1 + bb.x, 0.f), fmaxf(d1 * ay1 + bb.y, 0.f));
}

// ---------------- fused aggregate + GEMM64 ----------------
__global__ void __launch_bounds__(256, 2) fused_agg_gemm(const float* __restrict__ t,
                                                         const float* __restrict__ bias,
                                                         const float* __restrict__ W,
                                                         float* __restrict__ out, int n) {
    constexpr int AST = 36, WST = 72, NKC = 4;
    extern __shared__ uint32_t sm[];
    uint32_t* Ah = sm;                   // [128][36]
    uint32_t* Al = Ah + 128 * AST;
    uint32_t* Wh = Al + 128 * AST;       // [32][72]
    uint32_t* Wl = Wh + 32 * WST;

    int tid = threadIdx.x, wid = tid >> 5, lane = tid & 31;
    int rb = blockIdx.x * 128;
    int nrows = min(128, n - rb);

    for (int i = tid; i < 32 * 64; i += 256) {
        int k2 = i >> 6, nn = i & 63;
        uint32_t hi, lo;
        split2(W[(2 * k2) * 64 + nn], W[(2 * k2 + 1) * 64 + nn], hi, lo);
        Wh[k2 * WST + nn] = hi;
        Wl[k2 * WST + nn] = lo;
    }

    // phase 1: 8 node-pairs per warp, interleaved gathers
    {
        int c2 = lane;
        float2 bb = __ldg((const float2*)bias + c2);
#pragma unroll 1
        for (int p = 0; p < 8; p++) {
            int r = wid * 16 + 2 * p;
            float2 h0 = make_float2(0.f, 0.f), h1 = make_float2(0.f, 0.f);
            if (r + 1 < nrows) {
                agg_pair(t, rb + r, rb + r + 1, c2, bb, h0, h1);
            } else if (r < nrows) {
                h0 = agg_node(t, rb + r, c2, bb);
            }
            uint32_t hi0, lo0, hi1, lo1;
            split2(h0.x, h0.y, hi0, lo0);
            split2(h1.x, h1.y, hi1, lo1);
            Ah[r * AST + c2] = hi0;
            Al[r * AST + c2] = lo0;
            Ah[(r + 1) * AST + c2] = hi1;
            Al[(r + 1) * AST + c2] = lo1;
        }
    }
    __syncthreads();

    // phase 2: MMA from smem
    int qr = lane >> 2, qc = lane & 3;
    int r0 = wid * 16 + qr;
    float acc[8][4];
#pragma unroll
    for (int t8 = 0; t8 < 8; t8++)
#pragma unroll
        for (int j = 0; j < 4; j++) acc[t8][j] = 0.f;

#pragma unroll
    for (int kc = 0; kc < NKC; kc++) {
        int ab = r0 * AST + kc * 8 + qc;
        uint32_t ah[4], al[4];
        ah[0] = Ah[ab];         ah[1] = Ah[ab + 8 * AST];
        ah[2] = Ah[ab + 4];     ah[3] = Ah[ab + 8 * AST + 4];
        al[0] = Al[ab];         al[1] = Al[ab + 8 * AST];
        al[2] = Al[ab + 4];     al[3] = Al[ab + 8 * AST + 4];
        int bb2 = (kc * 8 + qc) * WST + qr;
#pragma unroll
        for (int t8 = 0; t8 < 8; t8++) {
            uint32_t bh0 = Wh[bb2 + 8 * t8];
            uint32_t bh1 = Wh[bb2 + 4 * WST + 8 * t8];
            uint32_t bl0 = Wl[bb2 + 8 * t8];
            uint32_t bl1 = Wl[bb2 + 4 * WST + 8 * t8];
            MMA_BF16(acc[t8], ah, bh0, bh1);
            MMA_BF16(acc[t8], ah, bl0, bl1);
            MMA_BF16(acc[t8], al, bh0, bh1);
        }
    }

    bool ok0 = (r0 < nrows), ok1 = (r0 + 8 < nrows);
    float* o0 = out + (size_t)(rb + r0) * 64;
    float* o1 = out + (size_t)(rb + r0 + 8) * 64;
#pragma unroll
    for (int t8 = 0; t8 < 8; t8++) {
        int c = 8 * t8 + qc * 2;
        if (ok0) *(float2*)(o0 + c) = make_float2(acc[t8][0], acc[t8][1]);
        if (ok1) *(float2*)(o1 + c) = make_float2(acc[t8][2], acc[t8][3]);
    }
}

// ---------------- fused aggregate + pool (paired) ----------------
__global__ void fused_agg_pool(const float* __restrict__ t, const float* __restrict__ bias,
                               const void* __restrict__ batch, int n) {
    int tid = threadIdx.x, wid = tid >> 5, lane = tid & 31;
    int is64 = g_idx64;
    int c2 = lane;
    float2 bb = __ldg((const float2*)bias + c2);
    int base = blockIdx.x * 128 + wid * 16;

    int curg = -1, lc = 0;
    float lsx = 0.f, lsy = 0.f, lmx = 0.f, lmy = 0.f;

    auto flush = [&]() {
        if (curg >= 0) {
            atomicAdd(&d_gsum[curg * HID + 2 * c2], lsx);
            atomicAdd(&d_gsum[curg * HID + 2 * c2 + 1], lsy);
            atomicMax(&d_gmax[curg * HID + 2 * c2], __float_as_uint(lmx));
            atomicMax(&d_gmax[curg * HID + 2 * c2 + 1], __float_as_uint(lmy));
            if (lane == 0) atomicAdd(&d_cnt[curg], lc);
        }
    };
    auto take = [&](int i, float2 h) {
        int g = ld_idx32(batch, i, is64);
        if (g != curg) {
            flush();
            curg = g; lsx = lsy = lmx = lmy = 0.f; lc = 0;
        }
        lsx += h.x; lsy += h.y;
        lmx = fmaxf(lmx, h.x); lmy = fmaxf(lmy, h.y);
        lc++;
    };

#pragma unroll 1
    for (int p = 0; p < 8; p++) {
        int i = base + 2 * p;
        if (i >= n) break;
        if (i + 1 < n) {
            float2 h0, h1;
            agg_pair(t, i, i + 1, c2, bb, h0, h1);
            take(i, h0);
            take(i + 1, h1);
        } else {
            take(i, agg_node(t, i, c2, bb));
        }
    }
    flush();
}

// ---------------- final ----------------
__global__ void final_kernel(const float* __restrict__ Wout, const float* __restrict__ bout,
                             float* __restrict__ out) {
    __shared__ float p[2 * HID];
    int g = blockIdx.x;
    int t = threadIdx.x;  // 128
    if (t < HID) {
        float cn = fmaxf((float)d_cnt[g], 1.f);
        p[t] = d_gsum[g * HID + t] / cn;
        p[HID + t] = __uint_as_float(d_gmax[g * HID + t]);
    }
    __syncthreads();
    if (t < NC) {
        float a = bout[t];
#pragma unroll 16
        for (int k = 0; k < 2 * HID; k++) a += p[k] * Wout[k * NC + t];
        out[g * NC + t] = a;
    }
}

// ---------------- launch ----------------
extern "C" void kernel_launch(void* const* d_in, const int* in_sizes, int n_in,
                              void* d_out, int out_size) {
    const float* x    = (const float*)d_in[0];
    const void*  ei   = d_in[1];
    const void*  bat  = d_in[2];
    const float* W0   = (const float*)d_in[3];
    const float* b0   = (const float*)d_in[4];
    const float* W1   = (const float*)d_in[5];
    const float* b1   = (const float*)d_in[6];
    const float* W2   = (const float*)d_in[7];
    const float* b2   = (const float*)d_in[8];
    const float* Wout = (const float*)d_in[9];
    const float* bout = (const float*)d_in[10];
    float* out = (float*)d_out;

    int N = in_sizes[2];
    int E = in_sizes[1] / 2;

    float *hp, *tp;
    cudaGetSymbolAddress((void**)&hp, d_hbuf);
    cudaGetSymbolAddress((void**)&tp, d_tbuf);

    int fsmem = (2 * 128 * 36 + 2 * 32 * 72) * 4;  // 55296
    cudaFuncSetAttribute(fused_agg_gemm, cudaFuncAttributeMaxDynamicSharedMemorySize, fsmem);

    int gblk = (N + 127) / 128;

    detect_kernel<<<1, 256>>>((const unsigned*)ei);
    zero_kernel<<<(N + 255) / 256, 256>>>(N);
    hist_kernel<<<(E + 255) / 256, 256>>>(ei, E);
    gemm_mma128<<<gblk, 256>>>(x, W0, tp, N);   // 4th launch -> profiled slot
    dinv_kernel<<<(N + 255) / 256, 256>>>(N);

    int nb = (N + SCAN_B - 1) / SCAN_B;
    scanA_kernel<<<nb, SCAN_T>>>(N);
    scanB_kernel<<<1, 512>>>(nb);
    scanC_kernel<<<(N + 255) / 256, 256>>>(N);
    scatter_kernel<<<(E + 255) / 256, 256>>>(ei, E);

    fused_agg_gemm<<<gblk, 256, fsmem>>>(tp, b0, W1, hp, N);
    fused_agg_gemm<<<gblk, 256, fsmem>>>(hp, b1, W2, tp, N);
    fused_agg_pool<<<gblk, 256>>>(tp, b2, bat, N);
    final_kernel<<<NG, 128>>>(Wout, bout, out);
}

// round 8
// speedup vs baseline: 2.3948x; 1.1866x over previous
#include <cuda_runtime.h>
#include <cuda_bf16.h>
#include <cstdint>

#define NN 500000
#define NE 1250000
#define HID 64
#define NG 512
#define NC 10

#define SCAN_T 256
#define SCAN_I 4
#define SCAN_B (SCAN_T*SCAN_I)   // 1024

// ---------------- device scratch ----------------
__device__ int      g_idx64;
__device__ int      d_degE[NN];
__device__ float    d_dinv[NN];
__device__ int      d_rowptr[NN];
__device__ int      d_cursor[NN];
__device__ int      d_bsums[512];
__device__ int      d_col[NE];
__device__ float    d_w[NE];
__device__ float    d_hbuf[(size_t)NN*HID];
__device__ float    d_tbuf[(size_t)NN*HID];
__device__ float    d_gsum[NG*HID];
__device__ unsigned d_gmax[NG*HID];
__device__ int      d_cnt[NG];

__device__ __forceinline__ int ld_idx32(const void* p, long long j, int is64) {
    const unsigned* u = (const unsigned*)p;
    return (int)(is64 ? u[2*j] : u[j]);
}

// ---------------- index-width detection ----------------
__global__ void detect_kernel(const unsigned* __restrict__ p) {
    __shared__ unsigned red[256];
    int t = threadIdx.x;
    unsigned v = 0;
    for (int i = 2 * t + 1; i < 4096; i += 512) v |= p[i];
    red[t] = v;
    __syncthreads();
    for (int off = 128; off > 0; off >>= 1) {
        if (t < off) red[t] |= red[t + off];
        __syncthreads();
    }
    if (t == 0) g_idx64 = (red[0] == 0) ? 1 : 0;
}

__global__ void zero_kernel(int n) {
    int i = blockIdx.x * blockDim.x + threadIdx.x;
    if (i < n) d_degE[i] = 0;
    if (i < NG * HID) { d_gsum[i] = 0.f; d_gmax[i] = 0u; }
    if (i < NG) d_cnt[i] = 0;
}

__global__ void hist_kernel(const void* __restrict__ ei, int E) {
    int e = blockIdx.x * blockDim.x + threadIdx.x;
    if (e >= E) return;
    int dd = ld_idx32(ei, (long long)E + e, g_idx64);
    atomicAdd(&d_degE[dd], 1);
}

__global__ void dinv_kernel(int n) {
    int i = blockIdx.x * blockDim.x + threadIdx.x;
    if (i < n) d_dinv[i] = rsqrtf((float)d_degE[i] + 1.0f);
}

// ---------------- exclusive scan ----------------
__global__ void scanA_kernel(int n) {
    __shared__ int sm[SCAN_T];
    int b = blockIdx.x, t = threadIdx.x;
    int base = b * SCAN_B + t * SCAN_I;
    int v[SCAN_I];
    int s = 0;
#pragma unroll
    for (int j = 0; j < SCAN_I; j++) {
        v[j] = (base + j < n) ? d_degE[base + j] : 0;
        s += v[j];
    }
    sm[t] = s;
    __syncthreads();
    for (int off = 1; off < SCAN_T; off <<= 1) {
        int x = (t >= off) ? sm[t - off] : 0;
        __syncthreads();
        sm[t] += x;
        __syncthreads();
    }
    int excl = (t > 0) ? sm[t - 1] : 0;
    if (t == SCAN_T - 1) d_bsums[b] = sm[t];
    int run = excl;
#pragma unroll
    for (int j = 0; j < SCAN_I; j++) {
        if (base + j < n) d_rowptr[base + j] = run;
        run += v[j];
    }
}

__global__ void scanB_kernel(int nb) {
    __shared__ int sm[512];
    int t = threadIdx.x;
    sm[t] = (t < nb) ? d_bsums[t] : 0;
    __syncthreads();
    for (int off = 1; off < 512; off <<= 1) {
        int x = (t >= off) ? sm[t - off] : 0;
        __syncthreads();
        sm[t] += x;
        __syncthreads();
    }
    int excl = (t > 0) ? sm[t - 1] : 0;
    if (t < nb) d_bsums[t] = excl;
}

__global__ void scanC_kernel(int n) {
    int i = blockIdx.x * blockDim.x + threadIdx.x;
    if (i < n) {
        int v = d_rowptr[i] + d_bsums[i / SCAN_B];
        d_rowptr[i] = v;
        d_cursor[i] = v;
    }
}

__global__ void scatter_kernel(const void* __restrict__ ei, int E) {
    int e = blockIdx.x * blockDim.x + threadIdx.x;
    if (e >= E) return;
    int is64 = g_idx64;
    int ss = ld_idx32(ei, e, is64);
    int dd = ld_idx32(ei, (long long)E + e, is64);
    int pos = atomicAdd(&d_cursor[dd], 1);
    d_col[pos] = ss;
    d_w[pos] = d_dinv[ss];
}

// ---------------- fast bf16x2 split ----------------
__device__ __forceinline__ void split2(float v0, float v1, uint32_t& hi, uint32_t& lo) {
    uint32_t h;
    asm("cvt.rn.bf16x2.f32 %0, %1, %2;" : "=r"(h) : "f"(v1), "f"(v0));
    float f0 = __uint_as_float(h << 16);
    float f1 = __uint_as_float(h & 0xFFFF0000u);
    asm("cvt.rn.bf16x2.f32 %0, %1, %2;" : "=r"(lo) : "f"(v1 - f1), "f"(v0 - f0));
    hi = h;
}

#define MMA_BF16(c, a, b0v, b1v) \
    asm volatile("mma.sync.aligned.m16n8k16.row.col.f32.bf16.bf16.f32 " \
        "{%0,%1,%2,%3}, {%4,%5,%6,%7}, {%8,%9}, {%0,%1,%2,%3};" \
        : "+f"((c)[0]), "+f"((c)[1]), "+f"((c)[2]), "+f"((c)[3]) \
        : "r"((a)[0]), "r"((a)[1]), "r"((a)[2]), "r"((a)[3]), "r"(b0v), "r"(b1v))

// ---------------- layer-0 GEMM: out[N,64] = in[N,128] @ W[128,64] ----------------
__global__ void __launch_bounds__(256, 2) gemm_mma128(const float* __restrict__ in,
                                                      const float* __restrict__ W,
                                                      float* __restrict__ out, int n) {
    constexpr int K = 128, K2 = 64, WST = 72, NKC = 8;
    __shared__ uint32_t Wh[K2 * WST];
    __shared__ uint32_t Wl[K2 * WST];

    int tid = threadIdx.x, wid = tid >> 5, lane = tid & 31;
    int rb = blockIdx.x * 128;
    int nrows = min(128, n - rb);

    for (int i = tid; i < K2 * 64; i += 256) {
        int p = i >> 6, nn = i & 63;
        int chunk = p >> 3, m = p & 7;
        int o = (chunk << 3) + ((m < 4) ? 2 * m : 2 * (m - 4) + 1);
        uint32_t hi, lo;
        split2(W[(2 * o) * 64 + nn], W[(2 * o + 1) * 64 + nn], hi, lo);
        Wh[p * WST + nn] = hi;
        Wl[p * WST + nn] = lo;
    }
    __syncthreads();

    int qr = lane >> 2, qc = lane & 3;
    int r0 = wid * 16 + qr;
    const float* base0 = in + (size_t)(rb + min(r0, nrows - 1)) * K;
    const float* base1 = in + (size_t)(rb + min(r0 + 8, nrows - 1)) * K;

    float acc[8][4];
#pragma unroll
    for (int t = 0; t < 8; t++)
#pragma unroll
        for (int j = 0; j < 4; j++) acc[t][j] = 0.f;

    float4 pf[2][2];
    pf[0][0] = __ldg((const float4*)(base0 + 4 * qc));
    pf[0][1] = __ldg((const float4*)(base1 + 4 * qc));
    pf[1][0] = __ldg((const float4*)(base0 + 16 + 4 * qc));
    pf[1][1] = __ldg((const float4*)(base1 + 16 + 4 * qc));

#pragma unroll
    for (int kc = 0; kc < NKC; kc++) {
        float4 a0 = pf[kc & 1][0], a1 = pf[kc & 1][1];
        if (kc + 2 < NKC) {
            int cn = (kc + 2) * 16 + 4 * qc;
            pf[kc & 1][0] = __ldg((const float4*)(base0 + cn));
            pf[kc & 1][1] = __ldg((const float4*)(base1 + cn));
        }
        uint32_t ah[4], al[4];
        split2(a0.x, a0.y, ah[0], al[0]);
        split2(a1.x, a1.y, ah[1], al[1]);
        split2(a0.z, a0.w, ah[2], al[2]);
        split2(a1.z, a1.w, ah[3], al[3]);

        int bb = (kc * 8 + qc) * WST + qr;
#pragma unroll
        for (int t = 0; t < 8; t++) {
            uint32_t bh0 = Wh[bb + 8 * t];
            uint32_t bh1 = Wh[bb + 4 * WST + 8 * t];
            uint32_t bl0 = Wl[bb + 8 * t];
            uint32_t bl1 = Wl[bb + 4 * WST + 8 * t];
            MMA_BF16(acc[t], ah, bh0, bh1);
            MMA_BF16(acc[t], ah, bl0, bl1);
            MMA_BF16(acc[t], al, bh0, bh1);
        }
    }

    bool ok0 = (r0 < nrows), ok1 = (r0 + 8 < nrows);
    float* o0 = out + (size_t)(rb + r0) * 64;
    float* o1 = out + (size_t)(rb + r0 + 8) * 64;
#pragma unroll
    for (int t = 0; t < 8; t++) {
        int c = 8 * t + qc * 2;
        if (ok0) *(float2*)(o0 + c) = make_float2(acc[t][0], acc[t][1]);
        if (ok1) *(float2*)(o1 + c) = make_float2(acc[t][2], acc[t][3]);
    }
}

// ---------------- single-node aggregate (tail path) ----------------
__device__ __forceinline__ float2 agg_node(const float* __restrict__ t, int i, int c2, float2 bb) {
    float di = d_dinv[i];
    const float2* t2 = (const float2*)t;
    float2 v = __ldg(t2 + (size_t)i * 32 + c2);
    float ax = di * v.x, ay = di * v.y;
    int start = d_rowptr[i];
    int cnt = d_degE[i];
    int j = 0;
    for (; j + 2 <= cnt; j += 2) {
        int s0 = d_col[start + j], s1 = d_col[start + j + 1];
        float w0 = d_w[start + j], w1 = d_w[start + j + 1];
        float2 u0 = __ldg(t2 + (size_t)s0 * 32 + c2);
        float2 u1 = __ldg(t2 + (size_t)s1 * 32 + c2);
        ax += w0 * u0.x; ay += w0 * u0.y;
        ax += w1 * u1.x; ay += w1 * u1.y;
    }
    if (j < cnt) {
        int s = d_col[start + j];
        float w = d_w[start + j];
        float2 u = __ldg(t2 + (size_t)s * 32 + c2);
        ax += w * u.x; ay += w * u.y;
    }
    return make_float2(fmaxf(di * ax + bb.x, 0.f), fmaxf(di * ay + bb.y, 0.f));
}

// ---------------- paired aggregate: two nodes, interleaved gathers (MLP 4) ----------------
__device__ __forceinline__ void agg_pair(const float* __restrict__ t, int i0, int i1,
                                         int c2, float2 bb, float2& h0, float2& h1) {
    const float2* t2 = (const float2*)t;
    float d0 = d_dinv[i0], d1 = d_dinv[i1];
    float2 v0 = __ldg(t2 + (size_t)i0 * 32 + c2);
    float2 v1 = __ldg(t2 + (size_t)i1 * 32 + c2);
    float ax0 = d0 * v0.x, ay0 = d0 * v0.y;
    float ax1 = d1 * v1.x, ay1 = d1 * v1.y;
    int r0 = d_rowptr[i0], n0 = d_degE[i0];
    int r1 = d_rowptr[i1], n1 = d_degE[i1];
    int m = min(n0, n1);
    int j = 0;
    for (; j + 2 <= m; j += 2) {
        int sa = d_col[r0 + j], sb = d_col[r0 + j + 1];
        int sc = d_col[r1 + j], sd = d_col[r1 + j + 1];
        float wa = d_w[r0 + j], wb = d_w[r0 + j + 1];
        float wc = d_w[r1 + j], wd = d_w[r1 + j + 1];
        float2 ua = __ldg(t2 + (size_t)sa * 32 + c2);
        float2 ub = __ldg(t2 + (size_t)sb * 32 + c2);
        float2 uc = __ldg(t2 + (size_t)sc * 32 + c2);
        float2 ud = __ldg(t2 + (size_t)sd * 32 + c2);
        ax0 += wa * ua.x; ay0 += wa * ua.y;
        ax1 += wc * uc.x; ay1 += wc * uc.y;
        ax0 += wb * ub.x; ay0 += wb * ub.y;
        ax1 += wd * ud.x; ay1 += wd * ud.y;
    }
    if (j < m) {
        int sa = d_col[r0 + j], sc = d_col[r1 + j];
        float wa = d_w[r0 + j], wc = d_w[r1 + j];
        float2 ua = __ldg(t2 + (size_t)sa * 32 + c2);
        float2 uc = __ldg(t2 + (size_t)sc * 32 + c2);
        ax0 += wa * ua.x; ay0 += wa * ua.y;
        ax1 += wc * uc.x; ay1 += wc * uc.y;
        j++;
    }
    int ja = j;
    for (; ja + 2 <= n0; ja += 2) {
        int sa = d_col[r0 + ja], sb = d_col[r0 + ja + 1];
        float wa = d_w[r0 + ja], wb = d_w[r0 + ja + 1];
        float2 ua = __ldg(t2 + (size_t)sa * 32 + c2);
        float2 ub = __ldg(t2 + (size_t)sb * 32 + c2);
        ax0 += wa * ua.x; ay0 += wa * ua.y;
        ax0 += wb * ub.x; ay0 += wb * ub.y;
    }
    if (ja < n0) {
        int sa = d_col[r0 + ja];
        float wa = d_w[r0 + ja];
        float2 ua = __ldg(t2 + (size_t)sa * 32 + c2);
        ax0 += wa * ua.x; ay0 += wa * ua.y;
    }
    int jb = j;
    for (; jb + 2 <= n1; jb += 2) {
        int sc = d_col[r1 + jb], sd = d_col[r1 + jb + 1];
        float wc = d_w[r1 + jb], wd = d_w[r1 + jb + 1];
        float2 uc = __ldg(t2 + (size_t)sc * 32 + c2);
        float2 ud = __ldg(t2 + (size_t)sd * 32 + c2);
        ax1 += wc * uc.x; ay1 += wc * uc.y;
        ax1 += wd * ud.x; ay1 += wd * ud.y;
    }
    if (jb < n1) {
        int sc = d_col[r1 + jb];
        float wc = d_w[r1 + jb];
        float2 uc = __ldg(t2 + (size_t)sc * 32 + c2);
        ax1 += wc * uc.x; ay1 += wc * uc.y;
    }
    h0 = make_float2(fmaxf(d0 * ax0 + bb.x, 0.f), fmaxf(d0 * ay0 + bb.y, 0.f));
    h1 = make_float2(fmaxf(d1 * ax1 + bb.x, 0.f), fmaxf(d1 * ay1 + bb.y, 0.f));
}

// ---------------- fused aggregate + GEMM64 (3 CTAs/SM for gather latency hiding) ----------------
__global__ void __launch_bounds__(256, 3) fused_agg_gemm(const float* __restrict__ t,
                                                         const float* __restrict__ bias,
                                                         const float* __restrict__ W,
                                                         float* __restrict__ out, int n) {
    constexpr int AST = 36, WST = 72, NKC = 4;
    extern __shared__ uint32_t sm[];
    uint32_t* Ah = sm;                   // [128][36]
    uint32_t* Al = Ah + 128 * AST;
    uint32_t* Wh = Al + 128 * AST;       // [32][72]
    uint32_t* Wl = Wh + 32 * WST;

    int tid = threadIdx.x, wid = tid >> 5, lane = tid & 31;
    int rb = blockIdx.x * 128;
    int nrows = min(128, n - rb);

    for (int i = tid; i < 32 * 64; i += 256) {
        int k2 = i >> 6, nn = i & 63;
        uint32_t hi, lo;
        split2(W[(2 * k2) * 64 + nn], W[(2 * k2 + 1) * 64 + nn], hi, lo);
        Wh[k2 * WST + nn] = hi;
        Wl[k2 * WST + nn] = lo;
    }

    // phase 1: 8 node-pairs per warp, interleaved gathers
    {
        int c2 = lane;
        float2 bb = __ldg((const float2*)bias + c2);
#pragma unroll 1
        for (int p = 0; p < 8; p++) {
            int r = wid * 16 + 2 * p;
            float2 h0 = make_float2(0.f, 0.f), h1 = make_float2(0.f, 0.f);
            if (r + 1 < nrows) {
                agg_pair(t, rb + r, rb + r + 1, c2, bb, h0, h1);
            } else if (r < nrows) {
                h0 = agg_node(t, rb + r, c2, bb);
            }
            uint32_t hi0, lo0, hi1, lo1;
            split2(h0.x, h0.y, hi0, lo0);
            split2(h1.x, h1.y, hi1, lo1);
            Ah[r * AST + c2] = hi0;
            Al[r * AST + c2] = lo0;
            Ah[(r + 1) * AST + c2] = hi1;
            Al[(r + 1) * AST + c2] = lo1;
        }
    }
    __syncthreads();

    // phase 2: MMA from smem
    int qr = lane >> 2, qc = lane & 3;
    int r0 = wid * 16 + qr;
    float acc[8][4];
#pragma unroll
    for (int t8 = 0; t8 < 8; t8++)
#pragma unroll
        for (int j = 0; j < 4; j++) acc[t8][j] = 0.f;

#pragma unroll
    for (int kc = 0; kc < NKC; kc++) {
        int ab = r0 * AST + kc * 8 + qc;
        uint32_t ah[4], al[4];
        ah[0] = Ah[ab];         ah[1] = Ah[ab + 8 * AST];
        ah[2] = Ah[ab + 4];     ah[3] = Ah[ab + 8 * AST + 4];
        al[0] = Al[ab];         al[1] = Al[ab + 8 * AST];
        al[2] = Al[ab + 4];     al[3] = Al[ab + 8 * AST + 4];
        int bb2 = (kc * 8 + qc) * WST + qr;
#pragma unroll
        for (int t8 = 0; t8 < 8; t8++) {
            uint32_t bh0 = Wh[bb2 + 8 * t8];
            uint32_t bh1 = Wh[bb2 + 4 * WST + 8 * t8];
            uint32_t bl0 = Wl[bb2 + 8 * t8];
            uint32_t bl1 = Wl[bb2 + 4 * WST + 8 * t8];
            MMA_BF16(acc[t8], ah, bh0, bh1);
            MMA_BF16(acc[t8], ah, bl0, bl1);
            MMA_BF16(acc[t8], al, bh0, bh1);
        }
    }

    bool ok0 = (r0 < nrows), ok1 = (r0 + 8 < nrows);
    float* o0 = out + (size_t)(rb + r0) * 64;
    float* o1 = out + (size_t)(rb + r0 + 8) * 64;
#pragma unroll
    for (int t8 = 0; t8 < 8; t8++) {
        int c = 8 * t8 + qc * 2;
        if (ok0) *(float2*)(o0 + c) = make_float2(acc[t8][0], acc[t8][1]);
        if (ok1) *(float2*)(o1 + c) = make_float2(acc[t8][2], acc[t8][3]);
    }
}

// ---------------- fused aggregate + pool (paired) ----------------
__global__ void fused_agg_pool(const float* __restrict__ t, const float* __restrict__ bias,
                               const void* __restrict__ batch, int n) {
    int tid = threadIdx.x, wid = tid >> 5, lane = tid & 31;
    int is64 = g_idx64;
    int c2 = lane;
    float2 bb = __ldg((const float2*)bias + c2);
    int base = blockIdx.x * 128 + wid * 16;

    int curg = -1, lc = 0;
    float lsx = 0.f, lsy = 0.f, lmx = 0.f, lmy = 0.f;

    auto flush = [&]() {
        if (curg >= 0) {
            atomicAdd(&d_gsum[curg * HID + 2 * c2], lsx);
            atomicAdd(&d_gsum[curg * HID + 2 * c2 + 1], lsy);
            atomicMax(&d_gmax[curg * HID + 2 * c2], __float_as_uint(lmx));
            atomicMax(&d_gmax[curg * HID + 2 * c2 + 1], __float_as_uint(lmy));
            if (lane == 0) atomicAdd(&d_cnt[curg], lc);
        }
    };
    auto take = [&](int i, float2 h) {
        int g = ld_idx32(batch, i, is64);
        if (g != curg) {
            flush();
            curg = g; lsx = lsy = lmx = lmy = 0.f; lc = 0;
        }
        lsx += h.x; lsy += h.y;
        lmx = fmaxf(lmx, h.x); lmy = fmaxf(lmy, h.y);
        lc++;
    };

#pragma unroll 1
    for (int p = 0; p < 8; p++) {
        int i = base + 2 * p;
        if (i >= n) break;
        if (i + 1 < n) {
            float2 h0, h1;
            agg_pair(t, i, i + 1, c2, bb, h0, h1);
            take(i, h0);
            take(i + 1, h1);
        } else {
            take(i, agg_node(t, i, c2, bb));
        }
    }
    flush();
}

// ---------------- final ----------------
__global__ void final_kernel(const float* __restrict__ Wout, const float* __restrict__ bout,
                             float* __restrict__ out) {
    __shared__ float p[2 * HID];
    int g = blockIdx.x;
    int t = threadIdx.x;  // 128
    if (t < HID) {
        float cn = fmaxf((float)d_cnt[g], 1.f);
        p[t] = d_gsum[g * HID + t] / cn;
        p[HID + t] = __uint_as_float(d_gmax[g * HID + t]);
    }
    __syncthreads();
    if (t < NC) {
        float a = bout[t];
#pragma unroll 16
        for (int k = 0; k < 2 * HID; k++) a += p[k] * Wout[k * NC + t];
        out[g * NC + t] = a;
    }
}

// ---------------- launch ----------------
extern "C" void kernel_launch(void* const* d_in, const int* in_sizes, int n_in,
                              void* d_out, int out_size) {
    const float* x    = (const float*)d_in[0];
    const void*  ei   = d_in[1];
    const void*  bat  = d_in[2];
    const float* W0   = (const float*)d_in[3];
    const float* b0   = (const float*)d_in[4];
    const float* W1   = (const float*)d_in[5];
    const float* b1   = (const float*)d_in[6];
    const float* W2   = (const float*)d_in[7];
    const float* b2   = (const float*)d_in[8];
    const float* Wout = (const float*)d_in[9];
    const float* bout = (const float*)d_in[10];
    float* out = (float*)d_out;

    int N = in_sizes[2];
    int E = in_sizes[1] / 2;

    float *hp, *tp;
    cudaGetSymbolAddress((void**)&hp, d_hbuf);
    cudaGetSymbolAddress((void**)&tp, d_tbuf);

    int fsmem = (2 * 128 * 36 + 2 * 32 * 72) * 4;  // 55296
    cudaFuncSetAttribute(fused_agg_gemm, cudaFuncAttributeMaxDynamicSharedMemorySize, fsmem);

    int gblk = (N + 127) / 128;

    // one-time side stream + events (reused across calls; no device memory involved)
    static cudaStream_t s2 = nullptr;
    static cudaEvent_t evFork = nullptr, evJoin = nullptr;
    if (s2 == nullptr) {
        cudaStreamCreateWithFlags(&s2, cudaStreamNonBlocking);
        cudaEventCreateWithFlags(&evFork, cudaEventDisableTiming);
        cudaEventCreateWithFlags(&evJoin, cudaEventDisableTiming);
    }

    // fork: CSR build on s2, layer-0 GEMM on main stream (independent inputs)
    cudaEventRecord(evFork, 0);
    cudaStreamWaitEvent(s2, evFork, 0);

    detect_kernel<<<1, 256, 0, s2>>>((const unsigned*)ei);
    zero_kernel<<<(N + 255) / 256, 256, 0, s2>>>(N);
    hist_kernel<<<(E + 255) / 256, 256, 0, s2>>>(ei, E);
    dinv_kernel<<<(N + 255) / 256, 256, 0, s2>>>(N);
    int nb = (N + SCAN_B - 1) / SCAN_B;
    scanA_kernel<<<nb, SCAN_T, 0, s2>>>(N);
    scanB_kernel<<<1, 512, 0, s2>>>(nb);
    scanC_kernel<<<(N + 255) / 256, 256, 0, s2>>>(N);
    scatter_kernel<<<(E + 255) / 256, 256, 0, s2>>>(ei, E);

    gemm_mma128<<<gblk, 256>>>(x, W0, tp, N);

    // join
    cudaEventRecord(evJoin, s2);
    cudaStreamWaitEvent(0, evJoin, 0);

    fused_agg_gemm<<<gblk, 256, fsmem>>>(tp, b0, W1, hp, N);
    fused_agg_gemm<<<gblk, 256, fsmem>>>(hp, b1, W2, tp, N);
    fused_agg_pool<<<gblk, 256>>>(tp, b2, bat, N);
    final_kernel<<<NG, 128>>>(Wout, bout, out);
}

// round 9
// speedup vs baseline: 2.5809x; 1.0777x over previous
#include <cuda_runtime.h>
#include <cuda_bf16.h>
#include <cstdint>

#define NN 500000
#define NE 1250000
#define HID 64
#define NG 512
#define NC 10

#define SCAN_T 256
#define SCAN_I 4
#define SCAN_B (SCAN_T*SCAN_I)   // 1024

// ---------------- device scratch ----------------
__device__ int      g_idx64;
__device__ int      d_degE[NN];
__device__ float    d_dinv[NN];
__device__ int      d_rowptr[NN];
__device__ int      d_cursor[NN];
__device__ int      d_bsums[512];
__device__ int      d_col[NE];
__device__ float    d_w[NE];
__device__ float    d_hbuf[(size_t)NN*HID];
__device__ float    d_tbuf[(size_t)NN*HID];
__device__ float    d_gsum[NG*HID];
__device__ unsigned d_gmax[NG*HID];
__device__ int      d_cnt[NG];

__device__ __forceinline__ int ld_idx32(const void* p, long long j, int is64) {
    const unsigned* u = (const unsigned*)p;
    return (int)(is64 ? u[2*j] : u[j]);
}

// ---------------- index-width detection ----------------
__global__ void detect_kernel(const unsigned* __restrict__ p) {
    __shared__ unsigned red[256];
    int t = threadIdx.x;
    unsigned v = 0;
    for (int i = 2 * t + 1; i < 4096; i += 512) v |= p[i];
    red[t] = v;
    __syncthreads();
    for (int off = 128; off > 0; off >>= 1) {
        if (t < off) red[t] |= red[t + off];
        __syncthreads();
    }
    if (t == 0) g_idx64 = (red[0] == 0) ? 1 : 0;
}

__global__ void zero_kernel(int n) {
    int i = blockIdx.x * blockDim.x + threadIdx.x;
    if (i < n) d_degE[i] = 0;
    if (i < NG * HID) { d_gsum[i] = 0.f; d_gmax[i] = 0u; }
    if (i < NG) d_cnt[i] = 0;
}

__global__ void hist_kernel(const void* __restrict__ ei, int E) {
    int e = blockIdx.x * blockDim.x + threadIdx.x;
    if (e >= E) return;
    int dd = ld_idx32(ei, (long long)E + e, g_idx64);
    atomicAdd(&d_degE[dd], 1);
}

__global__ void dinv_kernel(int n) {
    int i = blockIdx.x * blockDim.x + threadIdx.x;
    if (i < n) d_dinv[i] = rsqrtf((float)d_degE[i] + 1.0f);
}

// ---------------- exclusive scan ----------------
__global__ void scanA_kernel(int n) {
    __shared__ int sm[SCAN_T];
    int b = blockIdx.x, t = threadIdx.x;
    int base = b * SCAN_B + t * SCAN_I;
    int v[SCAN_I];
    int s = 0;
#pragma unroll
    for (int j = 0; j < SCAN_I; j++) {
        v[j] = (base + j < n) ? d_degE[base + j] : 0;
        s += v[j];
    }
    sm[t] = s;
    __syncthreads();
    for (int off = 1; off < SCAN_T; off <<= 1) {
        int x = (t >= off) ? sm[t - off] : 0;
        __syncthreads();
        sm[t] += x;
        __syncthreads();
    }
    int excl = (t > 0) ? sm[t - 1] : 0;
    if (t == SCAN_T - 1) d_bsums[b] = sm[t];
    int run = excl;
#pragma unroll
    for (int j = 0; j < SCAN_I; j++) {
        if (base + j < n) d_rowptr[base + j] = run;
        run += v[j];
    }
}

__global__ void scanB_kernel(int nb) {
    __shared__ int sm[512];
    int t = threadIdx.x;
    sm[t] = (t < nb) ? d_bsums[t] : 0;
    __syncthreads();
    for (int off = 1; off < 512; off <<= 1) {
        int x = (t >= off) ? sm[t - off] : 0;
        __syncthreads();
        sm[t] += x;
        __syncthreads();
    }
    int excl = (t > 0) ? sm[t - 1] : 0;
    if (t < nb) d_bsums[t] = excl;
}

__global__ void scanC_kernel(int n) {
    int i = blockIdx.x * blockDim.x + threadIdx.x;
    if (i < n) {
        int v = d_rowptr[i] + d_bsums[i / SCAN_B];
        d_rowptr[i] = v;
        d_cursor[i] = v;
    }
}

__global__ void scatter_kernel(const void* __restrict__ ei, int E) {
    int e = blockIdx.x * blockDim.x + threadIdx.x;
    if (e >= E) return;
    int is64 = g_idx64;
    int ss = ld_idx32(ei, e, is64);
    int dd = ld_idx32(ei, (long long)E + e, is64);
    int pos = atomicAdd(&d_cursor[dd], 1);
    d_col[pos] = ss;
    d_w[pos] = d_dinv[ss];
}

// ---------------- fast bf16x2 split ----------------
__device__ __forceinline__ void split2(float v0, float v1, uint32_t& hi, uint32_t& lo) {
    uint32_t h;
    asm("cvt.rn.bf16x2.f32 %0, %1, %2;" : "=r"(h) : "f"(v1), "f"(v0));
    float f0 = __uint_as_float(h << 16);
    float f1 = __uint_as_float(h & 0xFFFF0000u);
    asm("cvt.rn.bf16x2.f32 %0, %1, %2;" : "=r"(lo) : "f"(v1 - f1), "f"(v0 - f0));
    hi = h;
}

#define MMA_BF16(c, a, b0v, b1v) \
    asm volatile("mma.sync.aligned.m16n8k16.row.col.f32.bf16.bf16.f32 " \
        "{%0,%1,%2,%3}, {%4,%5,%6,%7}, {%8,%9}, {%0,%1,%2,%3};" \
        : "+f"((c)[0]), "+f"((c)[1]), "+f"((c)[2]), "+f"((c)[3]) \
        : "r"((a)[0]), "r"((a)[1]), "r"((a)[2]), "r"((a)[3]), "r"(b0v), "r"(b1v))

// ---------------- layer-0 GEMM: out[N,64] = in[N,128] @ W[128,64] ----------------
__global__ void __launch_bounds__(256, 2) gemm_mma128(const float* __restrict__ in,
                                                      const float* __restrict__ W,
                                                      float* __restrict__ out, int n) {
    constexpr int K = 128, K2 = 64, WST = 72, NKC = 8;
    __shared__ uint32_t Wh[K2 * WST];
    __shared__ uint32_t Wl[K2 * WST];

    int tid = threadIdx.x, wid = tid >> 5, lane = tid & 31;
    int rb = blockIdx.x * 128;
    int nrows = min(128, n - rb);

    for (int i = tid; i < K2 * 64; i += 256) {
        int p = i >> 6, nn = i & 63;
        int chunk = p >> 3, m = p & 7;
        int o = (chunk << 3) + ((m < 4) ? 2 * m : 2 * (m - 4) + 1);
        uint32_t hi, lo;
        split2(W[(2 * o) * 64 + nn], W[(2 * o + 1) * 64 + nn], hi, lo);
        Wh[p * WST + nn] = hi;
        Wl[p * WST + nn] = lo;
    }
    __syncthreads();

    int qr = lane >> 2, qc = lane & 3;
    int r0 = wid * 16 + qr;
    const float* base0 = in + (size_t)(rb + min(r0, nrows - 1)) * K;
    const float* base1 = in + (size_t)(rb + min(r0 + 8, nrows - 1)) * K;

    float acc[8][4];
#pragma unroll
    for (int t = 0; t < 8; t++)
#pragma unroll
        for (int j = 0; j < 4; j++) acc[t][j] = 0.f;

    float4 pf[2][2];
    pf[0][0] = __ldg((const float4*)(base0 + 4 * qc));
    pf[0][1] = __ldg((const float4*)(base1 + 4 * qc));
    pf[1][0] = __ldg((const float4*)(base0 + 16 + 4 * qc));
    pf[1][1] = __ldg((const float4*)(base1 + 16 + 4 * qc));

#pragma unroll
    for (int kc = 0; kc < NKC; kc++) {
        float4 a0 = pf[kc & 1][0], a1 = pf[kc & 1][1];
        if (kc + 2 < NKC) {
            int cn = (kc + 2) * 16 + 4 * qc;
            pf[kc & 1][0] = __ldg((const float4*)(base0 + cn));
            pf[kc & 1][1] = __ldg((const float4*)(base1 + cn));
        }
        uint32_t ah[4], al[4];
        split2(a0.x, a0.y, ah[0], al[0]);
        split2(a1.x, a1.y, ah[1], al[1]);
        split2(a0.z, a0.w, ah[2], al[2]);
        split2(a1.z, a1.w, ah[3], al[3]);

        int bb = (kc * 8 + qc) * WST + qr;
#pragma unroll
        for (int t = 0; t < 8; t++) {
            uint32_t bh0 = Wh[bb + 8 * t];
            uint32_t bh1 = Wh[bb + 4 * WST + 8 * t];
            uint32_t bl0 = Wl[bb + 8 * t];
            uint32_t bl1 = Wl[bb + 4 * WST + 8 * t];
            MMA_BF16(acc[t], ah, bh0, bh1);
            MMA_BF16(acc[t], ah, bl0, bl1);
            MMA_BF16(acc[t], al, bh0, bh1);
        }
    }

    bool ok0 = (r0 < nrows), ok1 = (r0 + 8 < nrows);
    float* o0 = out + (size_t)(rb + r0) * 64;
    float* o1 = out + (size_t)(rb + r0 + 8) * 64;
#pragma unroll
    for (int t = 0; t < 8; t++) {
        int c = 8 * t + qc * 2;
        if (ok0) *(float2*)(o0 + c) = make_float2(acc[t][0], acc[t][1]);
        if (ok1) *(float2*)(o1 + c) = make_float2(acc[t][2], acc[t][3]);
    }
}

// ---------------- half-warp float4 aggregate with predicated 4-wide edge loop ----------------
// 16 lanes cover the 64-ch row; per iteration 4 gathers in flight per half-warp.
__device__ __forceinline__ float4 agg_node_f4(const float* __restrict__ t, int i,
                                              int c4, float4 bb) {
    const float4* t4 = (const float4*)t;   // 16 float4 per row
    float di = d_dinv[i];
    float4 v = __ldg(t4 + (size_t)i * 16 + c4);
    float ax = di * v.x, ay = di * v.y, az = di * v.z, aw = di * v.w;
    int start = d_rowptr[i];
    int cnt = d_degE[i];
    int iters = (cnt + 3) >> 2;
    for (int it = 0; it < iters; it++) {
        int j = it * 4;
        int lim = cnt - 1;
        int i0 = start + j;
        int i1 = start + min(j + 1, lim);
        int i2 = start + min(j + 2, lim);
        int i3 = start + min(j + 3, lim);
        int s0 = d_col[i0], s1 = d_col[i1], s2 = d_col[i2], s3 = d_col[i3];
        float w0 = d_w[i0];
        float w1 = (j + 1 <= lim) ? d_w[i1] : 0.f;
        float w2 = (j + 2 <= lim) ? d_w[i2] : 0.f;
        float w3 = (j + 3 <= lim) ? d_w[i3] : 0.f;
        float4 u0 = __ldg(t4 + (size_t)s0 * 16 + c4);
        float4 u1 = __ldg(t4 + (size_t)s1 * 16 + c4);
        float4 u2 = __ldg(t4 + (size_t)s2 * 16 + c4);
        float4 u3 = __ldg(t4 + (size_t)s3 * 16 + c4);
        ax += w0 * u0.x; ay += w0 * u0.y; az += w0 * u0.z; aw += w0 * u0.w;
        ax += w1 * u1.x; ay += w1 * u1.y; az += w1 * u1.z; aw += w1 * u1.w;
        ax += w2 * u2.x; ay += w2 * u2.y; az += w2 * u2.z; aw += w2 * u2.w;
        ax += w3 * u3.x; ay += w3 * u3.y; az += w3 * u3.z; aw += w3 * u3.w;
    }
    return make_float4(fmaxf(di * ax + bb.x, 0.f), fmaxf(di * ay + bb.y, 0.f),
                       fmaxf(di * az + bb.z, 0.f), fmaxf(di * aw + bb.w, 0.f));
}

// ---------------- fused aggregate + GEMM64 ----------------
__global__ void __launch_bounds__(256, 3) fused_agg_gemm(const float* __restrict__ t,
                                                         const float* __restrict__ bias,
                                                         const float* __restrict__ W,
                                                         float* __restrict__ out, int n) {
    constexpr int AST = 36, WST = 72, NKC = 4;
    extern __shared__ uint32_t sm[];
    uint32_t* Ah = sm;                   // [128][36]
    uint32_t* Al = Ah + 128 * AST;
    uint32_t* Wh = Al + 128 * AST;       // [32][72]
    uint32_t* Wl = Wh + 32 * WST;

    int tid = threadIdx.x, wid = tid >> 5, lane = tid & 31;
    int rb = blockIdx.x * 128;
    int nrows = min(128, n - rb);

    for (int i = tid; i < 32 * 64; i += 256) {
        int k2 = i >> 6, nn = i & 63;
        uint32_t hi, lo;
        split2(W[(2 * k2) * 64 + nn], W[(2 * k2 + 1) * 64 + nn], hi, lo);
        Wh[k2 * WST + nn] = hi;
        Wl[k2 * WST + nn] = lo;
    }

    // phase 1: half-warp per node, 8 nodes per half
    {
        int half = lane >> 4, c4 = lane & 15;
        float4 bb = __ldg((const float4*)bias + c4);
#pragma unroll 1
        for (int p = 0; p < 8; p++) {
            int r = wid * 16 + half * 8 + p;
            float4 h = make_float4(0.f, 0.f, 0.f, 0.f);
            if (r < nrows) h = agg_node_f4(t, rb + r, c4, bb);
            uint32_t hi0, lo0, hi1, lo1;
            split2(h.x, h.y, hi0, lo0);
            split2(h.z, h.w, hi1, lo1);
            Ah[r * AST + 2 * c4] = hi0;
            Ah[r * AST + 2 * c4 + 1] = hi1;
            Al[r * AST + 2 * c4] = lo0;
            Al[r * AST + 2 * c4 + 1] = lo1;
        }
    }
    __syncthreads();

    // phase 2: MMA from smem
    int qr = lane >> 2, qc = lane & 3;
    int r0 = wid * 16 + qr;
    float acc[8][4];
#pragma unroll
    for (int t8 = 0; t8 < 8; t8++)
#pragma unroll
        for (int j = 0; j < 4; j++) acc[t8][j] = 0.f;

#pragma unroll
    for (int kc = 0; kc < NKC; kc++) {
        int ab = r0 * AST + kc * 8 + qc;
        uint32_t ah[4], al[4];
        ah[0] = Ah[ab];         ah[1] = Ah[ab + 8 * AST];
        ah[2] = Ah[ab + 4];     ah[3] = Ah[ab + 8 * AST + 4];
        al[0] = Al[ab];         al[1] = Al[ab + 8 * AST];
        al[2] = Al[ab + 4];     al[3] = Al[ab + 8 * AST + 4];
        int bb2 = (kc * 8 + qc) * WST + qr;
#pragma unroll
        for (int t8 = 0; t8 < 8; t8++) {
            uint32_t bh0 = Wh[bb2 + 8 * t8];
            uint32_t bh1 = Wh[bb2 + 4 * WST + 8 * t8];
            uint32_t bl0 = Wl[bb2 + 8 * t8];
            uint32_t bl1 = Wl[bb2 + 4 * WST + 8 * t8];
            MMA_BF16(acc[t8], ah, bh0, bh1);
            MMA_BF16(acc[t8], ah, bl0, bl1);
            MMA_BF16(acc[t8], al, bh0, bh1);
        }
    }

    bool ok0 = (r0 < nrows), ok1 = (r0 + 8 < nrows);
    float* o0 = out + (size_t)(rb + r0) * 64;
    float* o1 = out + (size_t)(rb + r0 + 8) * 64;
#pragma unroll
    for (int t8 = 0; t8 < 8; t8++) {
        int c = 8 * t8 + qc * 2;
        if (ok0) *(float2*)(o0 + c) = make_float2(acc[t8][0], acc[t8][1]);
        if (ok1) *(float2*)(o1 + c) = make_float2(acc[t8][2], acc[t8][3]);
    }
}

// ---------------- fused aggregate + pool (half-warp per node, contiguous blocks) ----------------
__global__ void fused_agg_pool(const float* __restrict__ t, const float* __restrict__ bias,
                               const void* __restrict__ batch, int n) {
    int tid = threadIdx.x, wid = tid >> 5, lane = tid & 31;
    int half = lane >> 4, c4 = lane & 15;
    int is64 = g_idx64;
    float4 bb = __ldg((const float4*)bias + c4);
    int base = blockIdx.x * 128 + wid * 16 + half * 8;

    int curg = -1, lc = 0;
    float4 ls = make_float4(0.f, 0.f, 0.f, 0.f);
    float4 lm = make_float4(0.f, 0.f, 0.f, 0.f);

    auto flush = [&]() {
        if (curg >= 0) {
            int o = curg * HID + 4 * c4;
            atomicAdd(&d_gsum[o + 0], ls.x);
            atomicAdd(&d_gsum[o + 1], ls.y);
            atomicAdd(&d_gsum[o + 2], ls.z);
            atomicAdd(&d_gsum[o + 3], ls.w);
            atomicMax(&d_gmax[o + 0], __float_as_uint(lm.x));
            atomicMax(&d_gmax[o + 1], __float_as_uint(lm.y));
            atomicMax(&d_gmax[o + 2], __float_as_uint(lm.z));
            atomicMax(&d_gmax[o + 3], __float_as_uint(lm.w));
            if (c4 == 0) atomicAdd(&d_cnt[curg], lc);
        }
    };

#pragma unroll 1
    for (int p = 0; p < 8; p++) {
        int i = base + p;
        if (i >= n) break;
        int g = ld_idx32(batch, i, is64);
        if (g != curg) {
            flush();
            curg = g; lc = 0;
            ls = make_float4(0.f, 0.f, 0.f, 0.f);
            lm = make_float4(0.f, 0.f, 0.f, 0.f);
        }
        float4 h = agg_node_f4(t, i, c4, bb);
        ls.x += h.x; ls.y += h.y; ls.z += h.z; ls.w += h.w;
        lm.x = fmaxf(lm.x, h.x); lm.y = fmaxf(lm.y, h.y);
        lm.z = fmaxf(lm.z, h.z); lm.w = fmaxf(lm.w, h.w);
        lc++;
    }
    flush();
}

// ---------------- final ----------------
__global__ void final_kernel(const float* __restrict__ Wout, const float* __restrict__ bout,
                             float* __restrict__ out) {
    __shared__ float p[2 * HID];
    int g = blockIdx.x;
    int t = threadIdx.x;  // 128
    if (t < HID) {
        float cn = fmaxf((float)d_cnt[g], 1.f);
        p[t] = d_gsum[g * HID + t] / cn;
        p[HID + t] = __uint_as_float(d_gmax[g * HID + t]);
    }
    __syncthreads();
    if (t < NC) {
        float a = bout[t];
#pragma unroll 16
        for (int k = 0; k < 2 * HID; k++) a += p[k] * Wout[k * NC + t];
        out[g * NC + t] = a;
    }
}

// ---------------- launch ----------------
extern "C" void kernel_launch(void* const* d_in, const int* in_sizes, int n_in,
                              void* d_out, int out_size) {
    const float* x    = (const float*)d_in[0];
    const void*  ei   = d_in[1];
    const void*  bat  = d_in[2];
    const float* W0   = (const float*)d_in[3];
    const float* b0   = (const float*)d_in[4];
    const float* W1   = (const float*)d_in[5];
    const float* b1   = (const float*)d_in[6];
    const float* W2   = (const float*)d_in[7];
    const float* b2   = (const float*)d_in[8];
    const float* Wout = (const float*)d_in[9];
    const float* bout = (const float*)d_in[10];
    float* out = (float*)d_out;

    int N = in_sizes[2];
    int E = in_sizes[1] / 2;

    float *hp, *tp;
    cudaGetSymbolAddress((void**)&hp, d_hbuf);
    cudaGetSymbolAddress((void**)&tp, d_tbuf);

    int fsmem = (2 * 128 * 36 + 2 * 32 * 72) * 4;  // 55296
    cudaFuncSetAttribute(fused_agg_gemm, cudaFuncAttributeMaxDynamicSharedMemorySize, fsmem);

    int gblk = (N + 127) / 128;

    static cudaStream_t s2 = nullptr;
    static cudaEvent_t evFork = nullptr, evJoin = nullptr;
    if (s2 == nullptr) {
        cudaStreamCreateWithFlags(&s2, cudaStreamNonBlocking);
        cudaEventCreateWithFlags(&evFork, cudaEventDisableTiming);
        cudaEventCreateWithFlags(&evJoin, cudaEventDisableTiming);
    }

    // fork: CSR build on s2, layer-0 GEMM on main stream
    cudaEventRecord(evFork, 0);
    cudaStreamWaitEvent(s2, evFork, 0);

    detect_kernel<<<1, 256, 0, s2>>>((const unsigned*)ei);
    zero_kernel<<<(N + 255) / 256, 256, 0, s2>>>(N);
    hist_kernel<<<(E + 255) / 256, 256, 0, s2>>>(ei, E);
    dinv_kernel<<<(N + 255) / 256, 256, 0, s2>>>(N);
    int nb = (N + SCAN_B - 1) / SCAN_B;
    scanA_kernel<<<nb, SCAN_T, 0, s2>>>(N);
    scanB_kernel<<<1, 512, 0, s2>>>(nb);
    scanC_kernel<<<(N + 255) / 256, 256, 0, s2>>>(N);
    scatter_kernel<<<(E + 255) / 256, 256, 0, s2>>>(ei, E);

    gemm_mma128<<<gblk, 256>>>(x, W0, tp, N);

    cudaEventRecord(evJoin, s2);
    cudaStreamWaitEvent(0, evJoin, 0);

    fused_agg_gemm<<<gblk, 256, fsmem>>>(tp, b0, W1, hp, N);
    fused_agg_gemm<<<gblk, 256, fsmem>>>(hp, b1, W2, tp, N);
    fused_agg_pool<<<gblk, 256>>>(tp, b2, bat, N);
    final_kernel<<<NG, 128>>>(Wout, bout, out);
}

// round 10
// speedup vs baseline: 2.9226x; 1.1324x over previous
#include <cuda_runtime.h>
#include <cuda_bf16.h>
#include <cuda_fp16.h>
#include <cstdint>

#define NN 500000
#define NE 1250000
#define HID 64
#define NG 512
#define NC 10

#define SCAN_T 256
#define SCAN_I 4
#define SCAN_B (SCAN_T*SCAN_I)   // 1024

// ---------------- device scratch ----------------
__device__ int      g_idx64;
__device__ int      d_degE[NN];
__device__ float    d_dinv[NN];
__device__ int      d_rowptr[NN];
__device__ int      d_cursor[NN];
__device__ int      d_bsums[512];
__device__ int      d_col[NE];
__device__ float    d_w[NE];
__device__ __half   d_hbuf[(size_t)NN*HID];
__device__ __half   d_tbuf[(size_t)NN*HID];
__device__ float    d_gsum[NG*HID];
__device__ unsigned d_gmax[NG*HID];
__device__ int      d_cnt[NG];

__device__ __forceinline__ int ld_idx32(const void* p, long long j, int is64) {
    const unsigned* u = (const unsigned*)p;
    return (int)(is64 ? u[2*j] : u[j]);
}

// ---------------- index-width detection ----------------
__global__ void detect_kernel(const unsigned* __restrict__ p) {
    __shared__ unsigned red[256];
    int t = threadIdx.x;
    unsigned v = 0;
    for (int i = 2 * t + 1; i < 4096; i += 512) v |= p[i];
    red[t] = v;
    __syncthreads();
    for (int off = 128; off > 0; off >>= 1) {
        if (t < off) red[t] |= red[t + off];
        __syncthreads();
    }
    if (t == 0) g_idx64 = (red[0] == 0) ? 1 : 0;
}

__global__ void zero_kernel(int n) {
    int i = blockIdx.x * blockDim.x + threadIdx.x;
    if (i < n) d_degE[i] = 0;
    if (i < NG * HID) { d_gsum[i] = 0.f; d_gmax[i] = 0u; }
    if (i < NG) d_cnt[i] = 0;
}

__global__ void hist_kernel(const void* __restrict__ ei, int E) {
    int e = blockIdx.x * blockDim.x + threadIdx.x;
    if (e >= E) return;
    int dd = ld_idx32(ei, (long long)E + e, g_idx64);
    atomicAdd(&d_degE[dd], 1);
}

__global__ void dinv_kernel(int n) {
    int i = blockIdx.x * blockDim.x + threadIdx.x;
    if (i < n) d_dinv[i] = rsqrtf((float)d_degE[i] + 1.0f);
}

// ---------------- exclusive scan ----------------
__global__ void scanA_kernel(int n) {
    __shared__ int sm[SCAN_T];
    int b = blockIdx.x, t = threadIdx.x;
    int base = b * SCAN_B + t * SCAN_I;
    int v[SCAN_I];
    int s = 0;
#pragma unroll
    for (int j = 0; j < SCAN_I; j++) {
        v[j] = (base + j < n) ? d_degE[base + j] : 0;
        s += v[j];
    }
    sm[t] = s;
    __syncthreads();
    for (int off = 1; off < SCAN_T; off <<= 1) {
        int x = (t >= off) ? sm[t - off] : 0;
        __syncthreads();
        sm[t] += x;
        __syncthreads();
    }
    int excl = (t > 0) ? sm[t - 1] : 0;
    if (t == SCAN_T - 1) d_bsums[b] = sm[t];
    int run = excl;
#pragma unroll
    for (int j = 0; j < SCAN_I; j++) {
        if (base + j < n) d_rowptr[base + j] = run;
        run += v[j];
    }
}

__global__ void scanB_kernel(int nb) {
    __shared__ int sm[512];
    int t = threadIdx.x;
    sm[t] = (t < nb) ? d_bsums[t] : 0;
    __syncthreads();
    for (int off = 1; off < 512; off <<= 1) {
        int x = (t >= off) ? sm[t - off] : 0;
        __syncthreads();
        sm[t] += x;
        __syncthreads();
    }
    int excl = (t > 0) ? sm[t - 1] : 0;
    if (t < nb) d_bsums[t] = excl;
}

__global__ void scanC_kernel(int n) {
    int i = blockIdx.x * blockDim.x + threadIdx.x;
    if (i < n) {
        int v = d_rowptr[i] + d_bsums[i / SCAN_B];
        d_rowptr[i] = v;
        d_cursor[i] = v;
    }
}

__global__ void scatter_kernel(const void* __restrict__ ei, int E) {
    int e = blockIdx.x * blockDim.x + threadIdx.x;
    if (e >= E) return;
    int is64 = g_idx64;
    int ss = ld_idx32(ei, e, is64);
    int dd = ld_idx32(ei, (long long)E + e, is64);
    int pos = atomicAdd(&d_cursor[dd], 1);
    d_col[pos] = ss;
    d_w[pos] = d_dinv[ss];
}

// ---------------- fast bf16x2 split ----------------
__device__ __forceinline__ void split2(float v0, float v1, uint32_t& hi, uint32_t& lo) {
    uint32_t h;
    asm("cvt.rn.bf16x2.f32 %0, %1, %2;" : "=r"(h) : "f"(v1), "f"(v0));
    float f0 = __uint_as_float(h << 16);
    float f1 = __uint_as_float(h & 0xFFFF0000u);
    asm("cvt.rn.bf16x2.f32 %0, %1, %2;" : "=r"(lo) : "f"(v1 - f1), "f"(v0 - f0));
    hi = h;
}

#define MMA_BF16(c, a, b0v, b1v) \
    asm volatile("mma.sync.aligned.m16n8k16.row.col.f32.bf16.bf16.f32 " \
        "{%0,%1,%2,%3}, {%4,%5,%6,%7}, {%8,%9}, {%0,%1,%2,%3};" \
        : "+f"((c)[0]), "+f"((c)[1]), "+f"((c)[2]), "+f"((c)[3]) \
        : "r"((a)[0]), "r"((a)[1]), "r"((a)[2]), "r"((a)[3]), "r"(b0v), "r"(b1v))

// ---------------- layer-0 GEMM: t[N,64] = in[N,128] @ W[128,64], fp16 output ----------------
__global__ void __launch_bounds__(256, 2) gemm_mma128(const float* __restrict__ in,
                                                      const float* __restrict__ W,
                                                      __half* __restrict__ out, int n) {
    constexpr int K = 128, K2 = 64, WST = 72, NKC = 8;
    __shared__ uint32_t Wh[K2 * WST];
    __shared__ uint32_t Wl[K2 * WST];

    int tid = threadIdx.x, wid = tid >> 5, lane = tid & 31;
    int rb = blockIdx.x * 128;
    int nrows = min(128, n - rb);

    for (int i = tid; i < K2 * 64; i += 256) {
        int p = i >> 6, nn = i & 63;
        int chunk = p >> 3, m = p & 7;
        int o = (chunk << 3) + ((m < 4) ? 2 * m : 2 * (m - 4) + 1);
        uint32_t hi, lo;
        split2(W[(2 * o) * 64 + nn], W[(2 * o + 1) * 64 + nn], hi, lo);
        Wh[p * WST + nn] = hi;
        Wl[p * WST + nn] = lo;
    }
    __syncthreads();

    int qr = lane >> 2, qc = lane & 3;
    int r0 = wid * 16 + qr;
    const float* base0 = in + (size_t)(rb + min(r0, nrows - 1)) * K;
    const float* base1 = in + (size_t)(rb + min(r0 + 8, nrows - 1)) * K;

    float acc[8][4];
#pragma unroll
    for (int t = 0; t < 8; t++)
#pragma unroll
        for (int j = 0; j < 4; j++) acc[t][j] = 0.f;

    float4 pf[2][2];
    pf[0][0] = __ldg((const float4*)(base0 + 4 * qc));
    pf[0][1] = __ldg((const float4*)(base1 + 4 * qc));
    pf[1][0] = __ldg((const float4*)(base0 + 16 + 4 * qc));
    pf[1][1] = __ldg((const float4*)(base1 + 16 + 4 * qc));

#pragma unroll
    for (int kc = 0; kc < NKC; kc++) {
        float4 a0 = pf[kc & 1][0], a1 = pf[kc & 1][1];
        if (kc + 2 < NKC) {
            int cn = (kc + 2) * 16 + 4 * qc;
            pf[kc & 1][0] = __ldg((const float4*)(base0 + cn));
            pf[kc & 1][1] = __ldg((const float4*)(base1 + cn));
        }
        uint32_t ah[4], al[4];
        split2(a0.x, a0.y, ah[0], al[0]);
        split2(a1.x, a1.y, ah[1], al[1]);
        split2(a0.z, a0.w, ah[2], al[2]);
        split2(a1.z, a1.w, ah[3], al[3]);

        int bb = (kc * 8 + qc) * WST + qr;
#pragma unroll
        for (int t = 0; t < 8; t++) {
            uint32_t bh0 = Wh[bb + 8 * t];
            uint32_t bh1 = Wh[bb + 4 * WST + 8 * t];
            uint32_t bl0 = Wl[bb + 8 * t];
            uint32_t bl1 = Wl[bb + 4 * WST + 8 * t];
            MMA_BF16(acc[t], ah, bh0, bh1);
            MMA_BF16(acc[t], ah, bl0, bl1);
            MMA_BF16(acc[t], al, bh0, bh1);
        }
    }

    bool ok0 = (r0 < nrows), ok1 = (r0 + 8 < nrows);
    __half* o0 = out + (size_t)(rb + r0) * 64;
    __half* o1 = out + (size_t)(rb + r0 + 8) * 64;
#pragma unroll
    for (int t = 0; t < 8; t++) {
        int c = 8 * t + qc * 2;
        if (ok0) *(__half2*)(o0 + c) = __floats2half2_rn(acc[t][0], acc[t][1]);
        if (ok1) *(__half2*)(o1 + c) = __floats2half2_rn(acc[t][2], acc[t][3]);
    }
}

// ---------------- half-warp fp16 aggregate: 16 lanes x uint2 = 128B row ----------------
__device__ __forceinline__ float4 agg_node_h4(const __half* __restrict__ t, int i,
                                              int c4, float4 bb) {
    const uint2* t2 = (const uint2*)t;   // 16 uint2 per 64-ch row
    float di = d_dinv[i];
    uint2 vv = __ldg(t2 + (size_t)i * 16 + c4);
    float2 va = __half22float2(*(const __half2*)&vv.x);
    float2 vb = __half22float2(*(const __half2*)&vv.y);
    float ax = di * va.x, ay = di * va.y, az = di * vb.x, aw = di * vb.y;
    int start = d_rowptr[i];
    int cnt = d_degE[i];
    int iters = (cnt + 3) >> 2;
    for (int it = 0; it < iters; it++) {
        int j = it * 4;
        int lim = cnt - 1;
        int i0 = start + j;
        int i1 = start + min(j + 1, lim);
        int i2 = start + min(j + 2, lim);
        int i3 = start + min(j + 3, lim);
        int s0 = d_col[i0], s1 = d_col[i1], s2 = d_col[i2], s3 = d_col[i3];
        float w0 = d_w[i0];
        float w1 = (j + 1 <= lim) ? d_w[i1] : 0.f;
        float w2 = (j + 2 <= lim) ? d_w[i2] : 0.f;
        float w3 = (j + 3 <= lim) ? d_w[i3] : 0.f;
        uint2 u0 = __ldg(t2 + (size_t)s0 * 16 + c4);
        uint2 u1 = __ldg(t2 + (size_t)s1 * 16 + c4);
        uint2 u2 = __ldg(t2 + (size_t)s2 * 16 + c4);
        uint2 u3 = __ldg(t2 + (size_t)s3 * 16 + c4);
        float2 a, b;
        a = __half22float2(*(const __half2*)&u0.x); b = __half22float2(*(const __half2*)&u0.y);
        ax += w0 * a.x; ay += w0 * a.y; az += w0 * b.x; aw += w0 * b.y;
        a = __half22float2(*(const __half2*)&u1.x); b = __half22float2(*(const __half2*)&u1.y);
        ax += w1 * a.x; ay += w1 * a.y; az += w1 * b.x; aw += w1 * b.y;
        a = __half22float2(*(const __half2*)&u2.x); b = __half22float2(*(const __half2*)&u2.y);
        ax += w2 * a.x; ay += w2 * a.y; az += w2 * b.x; aw += w2 * b.y;
        a = __half22float2(*(const __half2*)&u3.x); b = __half22float2(*(const __half2*)&u3.y);
        ax += w3 * a.x; ay += w3 * a.y; az += w3 * b.x; aw += w3 * b.y;
    }
    return make_float4(fmaxf(di * ax + bb.x, 0.f), fmaxf(di * ay + bb.y, 0.f),
                       fmaxf(di * az + bb.z, 0.f), fmaxf(di * aw + bb.w, 0.f));
}

// ---------------- fused aggregate + GEMM64 (fp16 in/out) ----------------
__global__ void __launch_bounds__(256, 3) fused_agg_gemm(const __half* __restrict__ t,
                                                         const float* __restrict__ bias,
                                                         const float* __restrict__ W,
                                                         __half* __restrict__ out, int n) {
    constexpr int AST = 36, WST = 72, NKC = 4;
    extern __shared__ uint32_t sm[];
    uint32_t* Ah = sm;                   // [128][36]
    uint32_t* Al = Ah + 128 * AST;
    uint32_t* Wh = Al + 128 * AST;       // [32][72]
    uint32_t* Wl = Wh + 32 * WST;

    int tid = threadIdx.x, wid = tid >> 5, lane = tid & 31;
    int rb = blockIdx.x * 128;
    int nrows = min(128, n - rb);

    for (int i = tid; i < 32 * 64; i += 256) {
        int k2 = i >> 6, nn = i & 63;
        uint32_t hi, lo;
        split2(W[(2 * k2) * 64 + nn], W[(2 * k2 + 1) * 64 + nn], hi, lo);
        Wh[k2 * WST + nn] = hi;
        Wl[k2 * WST + nn] = lo;
    }

    // phase 1: half-warp per node
    {
        int half = lane >> 4, c4 = lane & 15;
        float4 bb = __ldg((const float4*)bias + c4);
#pragma unroll 1
        for (int p = 0; p < 8; p++) {
            int r = wid * 16 + half * 8 + p;
            float4 h = make_float4(0.f, 0.f, 0.f, 0.f);
            if (r < nrows) h = agg_node_h4(t, rb + r, c4, bb);
            uint32_t hi0, lo0, hi1, lo1;
            split2(h.x, h.y, hi0, lo0);
            split2(h.z, h.w, hi1, lo1);
            Ah[r * AST + 2 * c4] = hi0;
            Ah[r * AST + 2 * c4 + 1] = hi1;
            Al[r * AST + 2 * c4] = lo0;
            Al[r * AST + 2 * c4 + 1] = lo1;
        }
    }
    __syncthreads();

    // phase 2: MMA from smem
    int qr = lane >> 2, qc = lane & 3;
    int r0 = wid * 16 + qr;
    float acc[8][4];
#pragma unroll
    for (int t8 = 0; t8 < 8; t8++)
#pragma unroll
        for (int j = 0; j < 4; j++) acc[t8][j] = 0.f;

#pragma unroll
    for (int kc = 0; kc < NKC; kc++) {
        int ab = r0 * AST + kc * 8 + qc;
        uint32_t ah[4], al[4];
        ah[0] = Ah[ab];         ah[1] = Ah[ab + 8 * AST];
        ah[2] = Ah[ab + 4];     ah[3] = Ah[ab + 8 * AST + 4];
        al[0] = Al[ab];         al[1] = Al[ab + 8 * AST];
        al[2] = Al[ab + 4];     al[3] = Al[ab + 8 * AST + 4];
        int bb2 = (kc * 8 + qc) * WST + qr;
#pragma unroll
        for (int t8 = 0; t8 < 8; t8++) {
            uint32_t bh0 = Wh[bb2 + 8 * t8];
            uint32_t bh1 = Wh[bb2 + 4 * WST + 8 * t8];
            uint32_t bl0 = Wl[bb2 + 8 * t8];
            uint32_t bl1 = Wl[bb2 + 4 * WST + 8 * t8];
            MMA_BF16(acc[t8], ah, bh0, bh1);
            MMA_BF16(acc[t8], ah, bl0, bl1);
            MMA_BF16(acc[t8], al, bh0, bh1);
        }
    }

    bool ok0 = (r0 < nrows), ok1 = (r0 + 8 < nrows);
    __half* o0 = out + (size_t)(rb + r0) * 64;
    __half* o1 = out + (size_t)(rb + r0 + 8) * 64;
#pragma unroll
    for (int t8 = 0; t8 < 8; t8++) {
        int c = 8 * t8 + qc * 2;
        if (ok0) *(__half2*)(o0 + c) = __floats2half2_rn(acc[t8][0], acc[t8][1]);
        if (ok1) *(__half2*)(o1 + c) = __floats2half2_rn(acc[t8][2], acc[t8][3]);
    }
}

// ---------------- fused aggregate + pool (fp16 gathers) ----------------
__global__ void fused_agg_pool(const __half* __restrict__ t, const float* __restrict__ bias,
                               const void* __restrict__ batch, int n) {
    int tid = threadIdx.x, wid = tid >> 5, lane = tid & 31;
    int half = lane >> 4, c4 = lane & 15;
    int is64 = g_idx64;
    float4 bb = __ldg((const float4*)bias + c4);
    int base = blockIdx.x * 128 + wid * 16 + half * 8;

    int curg = -1, lc = 0;
    float4 ls = make_float4(0.f, 0.f, 0.f, 0.f);
    float4 lm = make_float4(0.f, 0.f, 0.f, 0.f);

    auto flush = [&]() {
        if (curg >= 0) {
            int o = curg * HID + 4 * c4;
            atomicAdd(&d_gsum[o + 0], ls.x);
            atomicAdd(&d_gsum[o + 1], ls.y);
            atomicAdd(&d_gsum[o + 2], ls.z);
            atomicAdd(&d_gsum[o + 3], ls.w);
            atomicMax(&d_gmax[o + 0], __float_as_uint(lm.x));
            atomicMax(&d_gmax[o + 1], __float_as_uint(lm.y));
            atomicMax(&d_gmax[o + 2], __float_as_uint(lm.z));
            atomicMax(&d_gmax[o + 3], __float_as_uint(lm.w));
            if (c4 == 0) atomicAdd(&d_cnt[curg], lc);
        }
    };

#pragma unroll 1
    for (int p = 0; p < 8; p++) {
        int i = base + p;
        if (i >= n) break;
        int g = ld_idx32(batch, i, is64);
        if (g != curg) {
            flush();
            curg = g; lc = 0;
            ls = make_float4(0.f, 0.f, 0.f, 0.f);
            lm = make_float4(0.f, 0.f, 0.f, 0.f);
        }
        float4 h = agg_node_h4(t, i, c4, bb);
        ls.x += h.x; ls.y += h.y; ls.z += h.z; ls.w += h.w;
        lm.x = fmaxf(lm.x, h.x); lm.y = fmaxf(lm.y, h.y);
        lm.z = fmaxf(lm.z, h.z); lm.w = fmaxf(lm.w, h.w);
        lc++;
    }
    flush();
}

// ---------------- final ----------------
__global__ void final_kernel(const float* __restrict__ Wout, const float* __restrict__ bout,
                             float* __restrict__ out) {
    __shared__ float p[2 * HID];
    int g = blockIdx.x;
    int t = threadIdx.x;  // 128
    if (t < HID) {
        float cn = fmaxf((float)d_cnt[g], 1.f);
        p[t] = d_gsum[g * HID + t] / cn;
        p[HID + t] = __uint_as_float(d_gmax[g * HID + t]);
    }
    __syncthreads();
    if (t < NC) {
        float a = bout[t];
#pragma unroll 16
        for (int k = 0; k < 2 * HID; k++) a += p[k] * Wout[k * NC + t];
        out[g * NC + t] = a;
    }
}

// ---------------- launch ----------------
extern "C" void kernel_launch(void* const* d_in, const int* in_sizes, int n_in,
                              void* d_out, int out_size) {
    const float* x    = (const float*)d_in[0];
    const void*  ei   = d_in[1];
    const void*  bat  = d_in[2];
    const float* W0   = (const float*)d_in[3];
    const float* b0   = (const float*)d_in[4];
    const float* W1   = (const float*)d_in[5];
    const float* b1   = (const float*)d_in[6];
    const float* W2   = (const float*)d_in[7];
    const float* b2   = (const float*)d_in[8];
    const float* Wout = (const float*)d_in[9];
    const float* bout = (const float*)d_in[10];
    float* out = (float*)d_out;

    int N = in_sizes[2];
    int E = in_sizes[1] / 2;

    __half *hp, *tp;
    cudaGetSymbolAddress((void**)&hp, d_hbuf);
    cudaGetSymbolAddress((void**)&tp, d_tbuf);

    int fsmem = (2 * 128 * 36 + 2 * 32 * 72) * 4;  // 55296
    cudaFuncSetAttribute(fused_agg_gemm, cudaFuncAttributeMaxDynamicSharedMemorySize, fsmem);

    int gblk = (N + 127) / 128;

    static cudaStream_t s2 = nullptr;
    static cudaEvent_t evFork = nullptr, evJoin = nullptr;
    if (s2 == nullptr) {
        cudaStreamCreateWithFlags(&s2, cudaStreamNonBlocking);
        cudaEventCreateWithFlags(&evFork, cudaEventDisableTiming);
        cudaEventCreateWithFlags(&evJoin, cudaEventDisableTiming);
    }

    // fork: CSR build on s2, layer-0 GEMM on main stream
    cudaEventRecord(evFork, 0);
    cudaStreamWaitEvent(s2, evFork, 0);

    detect_kernel<<<1, 256, 0, s2>>>((const unsigned*)ei);
    zero_kernel<<<(N + 255) / 256, 256, 0, s2>>>(N);
    hist_kernel<<<(E + 255) / 256, 256, 0, s2>>>(ei, E);
    dinv_kernel<<<(N + 255) / 256, 256, 0, s2>>>(N);
    int nb = (N + SCAN_B - 1) / SCAN_B;
    scanA_kernel<<<nb, SCAN_T, 0, s2>>>(N);
    scanB_kernel<<<1, 512, 0, s2>>>(nb);
    scanC_kernel<<<(N + 255) / 256, 256, 0, s2>>>(N);
    scatter_kernel<<<(E + 255) / 256, 256, 0, s2>>>(ei, E);

    gemm_mma128<<<gblk, 256>>>(x, W0, tp, N);

    cudaEventRecord(evJoin, s2);
    cudaStreamWaitEvent(0, evJoin, 0);

    fused_agg_gemm<<<gblk, 256, fsmem>>>(tp, b0, W1, hp, N);
    fused_agg_gemm<<<gblk, 256, fsmem>>>(hp, b1, W2, tp, N);
    fused_agg_pool<<<gblk, 256>>>(tp, b2, bat, N);
    final_kernel<<<NG, 128>>>(Wout, bout, out);
}

// round 11
// speedup vs baseline: 2.9791x; 1.0193x over previous
#include <cuda_runtime.h>
#include <cuda_bf16.h>
#include <cuda_fp16.h>
#include <cstdint>

#define NN 500000
#define NE 1250000
#define HID 64
#define NG 512
#define NC 10

#define SCAN_T 256
#define SCAN_I 4
#define SCAN_B (SCAN_T*SCAN_I)   // 1024

// ---------------- device scratch ----------------
__device__ int      g_idx64;
__device__ int      d_degE[NN];
__device__ float    d_dinv[NN];
__device__ int      d_rowptr[NN];
__device__ int      d_cursor[NN];
__device__ int      d_bsums[512];
__device__ float4   d_metaf[NN];     // {rowptr, deg, dinv, -}
__device__ float2   d_colw[NE];      // {col bits, weight}
__device__ __half   d_hbuf[(size_t)NN*HID];
__device__ __half   d_tbuf[(size_t)NN*HID];
__device__ float    d_gsum[NG*HID];
__device__ unsigned d_gmax[NG*HID];
__device__ int      d_cnt[NG];

__device__ __forceinline__ int ld_idx32(const void* p, long long j, int is64) {
    const unsigned* u = (const unsigned*)p;
    return (int)(is64 ? u[2*j] : u[j]);
}

// ---------------- index-width detection ----------------
__global__ void detect_kernel(const unsigned* __restrict__ p) {
    __shared__ unsigned red[256];
    int t = threadIdx.x;
    unsigned v = 0;
    for (int i = 2 * t + 1; i < 4096; i += 512) v |= p[i];
    red[t] = v;
    __syncthreads();
    for (int off = 128; off > 0; off >>= 1) {
        if (t < off) red[t] |= red[t + off];
        __syncthreads();
    }
    if (t == 0) g_idx64 = (red[0] == 0) ? 1 : 0;
}

__global__ void zero_kernel(int n) {
    int i = blockIdx.x * blockDim.x + threadIdx.x;
    if (i < n) d_degE[i] = 0;
    if (i < NG * HID) { d_gsum[i] = 0.f; d_gmax[i] = 0u; }
    if (i < NG) d_cnt[i] = 0;
}

__global__ void hist_kernel(const void* __restrict__ ei, int E) {
    int e = blockIdx.x * blockDim.x + threadIdx.x;
    if (e >= E) return;
    int dd = ld_idx32(ei, (long long)E + e, g_idx64);
    atomicAdd(&d_degE[dd], 1);
}

__global__ void dinv_kernel(int n) {
    int i = blockIdx.x * blockDim.x + threadIdx.x;
    if (i < n) d_dinv[i] = rsqrtf((float)d_degE[i] + 1.0f);
}

// ---------------- exclusive scan ----------------
__global__ void scanA_kernel(int n) {
    __shared__ int sm[SCAN_T];
    int b = blockIdx.x, t = threadIdx.x;
    int base = b * SCAN_B + t * SCAN_I;
    int v[SCAN_I];
    int s = 0;
#pragma unroll
    for (int j = 0; j < SCAN_I; j++) {
        v[j] = (base + j < n) ? d_degE[base + j] : 0;
        s += v[j];
    }
    sm[t] = s;
    __syncthreads();
    for (int off = 1; off < SCAN_T; off <<= 1) {
        int x = (t >= off) ? sm[t - off] : 0;
        __syncthreads();
        sm[t] += x;
        __syncthreads();
    }
    int excl = (t > 0) ? sm[t - 1] : 0;
    if (t == SCAN_T - 1) d_bsums[b] = sm[t];
    int run = excl;
#pragma unroll
    for (int j = 0; j < SCAN_I; j++) {
        if (base + j < n) d_rowptr[base + j] = run;
        run += v[j];
    }
}

__global__ void scanB_kernel(int nb) {
    __shared__ int sm[512];
    int t = threadIdx.x;
    sm[t] = (t < nb) ? d_bsums[t] : 0;
    __syncthreads();
    for (int off = 1; off < 512; off <<= 1) {
        int x = (t >= off) ? sm[t - off] : 0;
        __syncthreads();
        sm[t] += x;
        __syncthreads();
    }
    int excl = (t > 0) ? sm[t - 1] : 0;
    if (t < nb) d_bsums[t] = excl;
}

__global__ void scanC_kernel(int n) {
    int i = blockIdx.x * blockDim.x + threadIdx.x;
    if (i < n) {
        int v = d_rowptr[i] + d_bsums[i / SCAN_B];
        d_cursor[i] = v;
        d_metaf[i] = make_float4(__int_as_float(v), __int_as_float(d_degE[i]), d_dinv[i], 0.f);
    }
}

__global__ void scatter_kernel(const void* __restrict__ ei, int E) {
    int e = blockIdx.x * blockDim.x + threadIdx.x;
    if (e >= E) return;
    int is64 = g_idx64;
    int ss = ld_idx32(ei, e, is64);
    int dd = ld_idx32(ei, (long long)E + e, is64);
    int pos = atomicAdd(&d_cursor[dd], 1);
    d_colw[pos] = make_float2(__int_as_float(ss), d_dinv[ss]);
}

// ---------------- fast bf16x2 split ----------------
__device__ __forceinline__ void split2(float v0, float v1, uint32_t& hi, uint32_t& lo) {
    uint32_t h;
    asm("cvt.rn.bf16x2.f32 %0, %1, %2;" : "=r"(h) : "f"(v1), "f"(v0));
    float f0 = __uint_as_float(h << 16);
    float f1 = __uint_as_float(h & 0xFFFF0000u);
    asm("cvt.rn.bf16x2.f32 %0, %1, %2;" : "=r"(lo) : "f"(v1 - f1), "f"(v0 - f0));
    hi = h;
}

#define MMA_BF16(c, a, b0v, b1v) \
    asm volatile("mma.sync.aligned.m16n8k16.row.col.f32.bf16.bf16.f32 " \
        "{%0,%1,%2,%3}, {%4,%5,%6,%7}, {%8,%9}, {%0,%1,%2,%3};" \
        : "+f"((c)[0]), "+f"((c)[1]), "+f"((c)[2]), "+f"((c)[3]) \
        : "r"((a)[0]), "r"((a)[1]), "r"((a)[2]), "r"((a)[3]), "r"(b0v), "r"(b1v))

// ---------------- layer-0 GEMM: t[N,64] = in[N,128] @ W[128,64], fp16 output ----------------
__global__ void __launch_bounds__(256, 2) gemm_mma128(const float* __restrict__ in,
                                                      const float* __restrict__ W,
                                                      __half* __restrict__ out, int n) {
    constexpr int K = 128, K2 = 64, WST = 72, NKC = 8;
    __shared__ uint32_t Wh[K2 * WST];
    __shared__ uint32_t Wl[K2 * WST];

    int tid = threadIdx.x, wid = tid >> 5, lane = tid & 31;
    int rb = blockIdx.x * 128;
    int nrows = min(128, n - rb);

    for (int i = tid; i < K2 * 64; i += 256) {
        int p = i >> 6, nn = i & 63;
        int chunk = p >> 3, m = p & 7;
        int o = (chunk << 3) + ((m < 4) ? 2 * m : 2 * (m - 4) + 1);
        uint32_t hi, lo;
        split2(W[(2 * o) * 64 + nn], W[(2 * o + 1) * 64 + nn], hi, lo);
        Wh[p * WST + nn] = hi;
        Wl[p * WST + nn] = lo;
    }
    __syncthreads();

    int qr = lane >> 2, qc = lane & 3;
    int r0 = wid * 16 + qr;
    const float* base0 = in + (size_t)(rb + min(r0, nrows - 1)) * K;
    const float* base1 = in + (size_t)(rb + min(r0 + 8, nrows - 1)) * K;

    float acc[8][4];
#pragma unroll
    for (int t = 0; t < 8; t++)
#pragma unroll
        for (int j = 0; j < 4; j++) acc[t][j] = 0.f;

    float4 pf[2][2];
    pf[0][0] = __ldg((const float4*)(base0 + 4 * qc));
    pf[0][1] = __ldg((const float4*)(base1 + 4 * qc));
    pf[1][0] = __ldg((const float4*)(base0 + 16 + 4 * qc));
    pf[1][1] = __ldg((const float4*)(base1 + 16 + 4 * qc));

#pragma unroll
    for (int kc = 0; kc < NKC; kc++) {
        float4 a0 = pf[kc & 1][0], a1 = pf[kc & 1][1];
        if (kc + 2 < NKC) {
            int cn = (kc + 2) * 16 + 4 * qc;
            pf[kc & 1][0] = __ldg((const float4*)(base0 + cn));
            pf[kc & 1][1] = __ldg((const float4*)(base1 + cn));
        }
        uint32_t ah[4], al[4];
        split2(a0.x, a0.y, ah[0], al[0]);
        split2(a1.x, a1.y, ah[1], al[1]);
        split2(a0.z, a0.w, ah[2], al[2]);
        split2(a1.z, a1.w, ah[3], al[3]);

        int bb = (kc * 8 + qc) * WST + qr;
#pragma unroll
        for (int t = 0; t < 8; t++) {
            uint32_t bh0 = Wh[bb + 8 * t];
            uint32_t bh1 = Wh[bb + 4 * WST + 8 * t];
            uint32_t bl0 = Wl[bb + 8 * t];
            uint32_t bl1 = Wl[bb + 4 * WST + 8 * t];
            MMA_BF16(acc[t], ah, bh0, bh1);
            MMA_BF16(acc[t], ah, bl0, bl1);
            MMA_BF16(acc[t], al, bh0, bh1);
        }
    }

    bool ok0 = (r0 < nrows), ok1 = (r0 + 8 < nrows);
    __half* o0 = out + (size_t)(rb + r0) * 64;
    __half* o1 = out + (size_t)(rb + r0 + 8) * 64;
#pragma unroll
    for (int t = 0; t < 8; t++) {
        int c = 8 * t + qc * 2;
        if (ok0) *(__half2*)(o0 + c) = __floats2half2_rn(acc[t][0], acc[t][1]);
        if (ok1) *(__half2*)(o1 + c) = __floats2half2_rn(acc[t][2], acc[t][3]);
    }
}

// ---------------- pipelined aggregate helpers ----------------
// first-4-edge (col,w) load, clamped; deg==0 -> self index with w=0
__device__ __forceinline__ void load4cw(int start, int cnt, int selfi,
                                        int* idx, float* w) {
    int lim = cnt - 1;
    if (lim < 0) {
#pragma unroll
        for (int e = 0; e < 4; e++) { idx[e] = selfi; w[e] = 0.f; }
        return;
    }
#pragma unroll
    for (int e = 0; e < 4; e++) {
        float2 cw = __ldg(&d_colw[start + min(e, lim)]);
        idx[e] = __float_as_int(cw.x);
        w[e] = (e <= lim) ? cw.y : 0.f;
    }
}

// body: self value + first 4 edges (preloaded) + rare tail (cnt>4)
__device__ __forceinline__ float4 agg_body(const uint2* __restrict__ t2, int c4,
                                           float di, uint2 sv,
                                           const int* idx, const float* w,
                                           int start, int cnt, float4 bb) {
    float2 va = __half22float2(*(const __half2*)&sv.x);
    float2 vb = __half22float2(*(const __half2*)&sv.y);
    float ax = di * va.x, ay = di * va.y, az = di * vb.x, aw = di * vb.y;
    uint2 u0 = __ldg(t2 + (size_t)idx[0] * 16 + c4);
    uint2 u1 = __ldg(t2 + (size_t)idx[1] * 16 + c4);
    uint2 u2 = __ldg(t2 + (size_t)idx[2] * 16 + c4);
    uint2 u3 = __ldg(t2 + (size_t)idx[3] * 16 + c4);
    float2 a, b;
    a = __half22float2(*(const __half2*)&u0.x); b = __half22float2(*(const __half2*)&u0.y);
    ax += w[0] * a.x; ay += w[0] * a.y; az += w[0] * b.x; aw += w[0] * b.y;
    a = __half22float2(*(const __half2*)&u1.x); b = __half22float2(*(const __half2*)&u1.y);
    ax += w[1] * a.x; ay += w[1] * a.y; az += w[1] * b.x; aw += w[1] * b.y;
    a = __half22float2(*(const __half2*)&u2.x); b = __half22float2(*(const __half2*)&u2.y);
    ax += w[2] * a.x; ay += w[2] * a.y; az += w[2] * b.x; aw += w[2] * b.y;
    a = __half22float2(*(const __half2*)&u3.x); b = __half22float2(*(const __half2*)&u3.y);
    ax += w[3] * a.x; ay += w[3] * a.y; az += w[3] * b.x; aw += w[3] * b.y;
    // rare tail (deg > 4)
    for (int j = 4; j < cnt; j += 4) {
        int lim = cnt - 1;
        int i0 = start + j;
        int i1 = start + min(j + 1, lim);
        int i2 = start + min(j + 2, lim);
        int i3 = start + min(j + 3, lim);
        float2 c0 = __ldg(&d_colw[i0]);
        float2 c1 = __ldg(&d_colw[i1]);
        float2 c2 = __ldg(&d_colw[i2]);
        float2 c3 = __ldg(&d_colw[i3]);
        float w0 = c0.y;
        float w1 = (j + 1 <= lim) ? c1.y : 0.f;
        float w2 = (j + 2 <= lim) ? c2.y : 0.f;
        float w3 = (j + 3 <= lim) ? c3.y : 0.f;
        uint2 v0 = __ldg(t2 + (size_t)__float_as_int(c0.x) * 16 + c4);
        uint2 v1 = __ldg(t2 + (size_t)__float_as_int(c1.x) * 16 + c4);
        uint2 v2 = __ldg(t2 + (size_t)__float_as_int(c2.x) * 16 + c4);
        uint2 v3 = __ldg(t2 + (size_t)__float_as_int(c3.x) * 16 + c4);
        a = __half22float2(*(const __half2*)&v0.x); b = __half22float2(*(const __half2*)&v0.y);
        ax += w0 * a.x; ay += w0 * a.y; az += w0 * b.x; aw += w0 * b.y;
        a = __half22float2(*(const __half2*)&v1.x); b = __half22float2(*(const __half2*)&v1.y);
        ax += w1 * a.x; ay += w1 * a.y; az += w1 * b.x; aw += w1 * b.y;
        a = __half22float2(*(const __half2*)&v2.x); b = __half22float2(*(const __half2*)&v2.y);
        ax += w2 * a.x; ay += w2 * a.y; az += w2 * b.x; aw += w2 * b.y;
        a = __half22float2(*(const __half2*)&v3.x); b = __half22float2(*(const __half2*)&v3.y);
        ax += w3 * a.x; ay += w3 * a.y; az += w3 * b.x; aw += w3 * b.y;
    }
    return make_float4(fmaxf(di * ax + bb.x, 0.f), fmaxf(di * ay + bb.y, 0.f),
                       fmaxf(di * az + bb.z, 0.f), fmaxf(di * aw + bb.w, 0.f));
}

// ---------------- fused aggregate + GEMM64 (pipelined phase 1) ----------------
__global__ void __launch_bounds__(256, 3) fused_agg_gemm(const __half* __restrict__ t,
                                                         const float* __restrict__ bias,
                                                         const float* __restrict__ W,
                                                         __half* __restrict__ out, int n) {
    constexpr int AST = 36, WST = 72, NKC = 4;
    extern __shared__ uint32_t sm[];
    uint32_t* Ah = sm;                   // [128][36]
    uint32_t* Al = Ah + 128 * AST;
    uint32_t* Wh = Al + 128 * AST;       // [32][72]
    uint32_t* Wl = Wh + 32 * WST;

    int tid = threadIdx.x, wid = tid >> 5, lane = tid & 31;
    int rb = blockIdx.x * 128;
    int nrows = min(128, n - rb);

    for (int i = tid; i < 32 * 64; i += 256) {
        int k2 = i >> 6, nn = i & 63;
        uint32_t hi, lo;
        split2(W[(2 * k2) * 64 + nn], W[(2 * k2 + 1) * 64 + nn], hi, lo);
        Wh[k2 * WST + nn] = hi;
        Wl[k2 * WST + nn] = lo;
    }

    // phase 1: half-warp per node, software-pipelined across 8 nodes
    {
        int half = lane >> 4, c4 = lane & 15;
        const uint2* t2 = (const uint2*)t;
        float4 bb = __ldg((const float4*)bias + c4);
        int base = wid * 16 + half * 8;

        int icur = rb + min(base, nrows - 1);
        float4 mt = __ldg(&d_metaf[icur]);
        uint2 sv = __ldg(t2 + (size_t)icur * 16 + c4);
        int start = __float_as_int(mt.x), cnt = __float_as_int(mt.y);
        float di = mt.z;
        int idx[4]; float w4[4];
        load4cw(start, cnt, icur, idx, w4);

#pragma unroll 1
        for (int p = 0; p < 8; p++) {
            int rcur = base + p;
            bool curval = (rcur < nrows);
            // prefetch next node's meta + self row
            float4 mtn; uint2 svn; int inn = 0;
            if (p < 7) {
                inn = rb + min(base + p + 1, nrows - 1);
                mtn = __ldg(&d_metaf[inn]);
                svn = __ldg(t2 + (size_t)inn * 16 + c4);
            }
            float4 h = make_float4(0.f, 0.f, 0.f, 0.f);
            if (curval) h = agg_body(t2, c4, di, sv, idx, w4, start, cnt, bb);
            uint32_t hi0, lo0, hi1, lo1;
            split2(h.x, h.y, hi0, lo0);
            split2(h.z, h.w, hi1, lo1);
            Ah[rcur * AST + 2 * c4] = hi0;
            Ah[rcur * AST + 2 * c4 + 1] = hi1;
            Al[rcur * AST + 2 * c4] = lo0;
            Al[rcur * AST + 2 * c4 + 1] = lo1;
            if (p < 7) {
                start = __float_as_int(mtn.x); cnt = __float_as_int(mtn.y); di = mtn.z;
                sv = svn;
                load4cw(start, cnt, inn, idx, w4);
            }
        }
    }
    __syncthreads();

    // phase 2: MMA from smem
    int qr = lane >> 2, qc = lane & 3;
    int r0 = wid * 16 + qr;
    float acc[8][4];
#pragma unroll
    for (int t8 = 0; t8 < 8; t8++)
#pragma unroll
        for (int j = 0; j < 4; j++) acc[t8][j] = 0.f;

#pragma unroll
    for (int kc = 0; kc < NKC; kc++) {
        int ab = r0 * AST + kc * 8 + qc;
        uint32_t ah[4], al[4];
        ah[0] = Ah[ab];         ah[1] = Ah[ab + 8 * AST];
        ah[2] = Ah[ab + 4];     ah[3] = Ah[ab + 8 * AST + 4];
        al[0] = Al[ab];         al[1] = Al[ab + 8 * AST];
        al[2] = Al[ab + 4];     al[3] = Al[ab + 8 * AST + 4];
        int bb2 = (kc * 8 + qc) * WST + qr;
#pragma unroll
        for (int t8 = 0; t8 < 8; t8++) {
            uint32_t bh0 = Wh[bb2 + 8 * t8];
            uint32_t bh1 = Wh[bb2 + 4 * WST + 8 * t8];
            uint32_t bl0 = Wl[bb2 + 8 * t8];
            uint32_t bl1 = Wl[bb2 + 4 * WST + 8 * t8];
            MMA_BF16(acc[t8], ah, bh0, bh1);
            MMA_BF16(acc[t8], ah, bl0, bl1);
            MMA_BF16(acc[t8], al, bh0, bh1);
        }
    }

    bool ok0 = (r0 < nrows), ok1 = (r0 + 8 < nrows);
    __half* o0 = out + (size_t)(rb + r0) * 64;
    __half* o1 = out + (size_t)(rb + r0 + 8) * 64;
#pragma unroll
    for (int t8 = 0; t8 < 8; t8++) {
        int c = 8 * t8 + qc * 2;
        if (ok0) *(__half2*)(o0 + c) = __floats2half2_rn(acc[t8][0], acc[t8][1]);
        if (ok1) *(__half2*)(o1 + c) = __floats2half2_rn(acc[t8][2], acc[t8][3]);
    }
}

// ---------------- fused aggregate + pool (pipelined) ----------------
__global__ void fused_agg_pool(const __half* __restrict__ t, const float* __restrict__ bias,
                               const void* __restrict__ batch, int n) {
    int tid = threadIdx.x, wid = tid >> 5, lane = tid & 31;
    int half = lane >> 4, c4 = lane & 15;
    int is64 = g_idx64;
    const uint2* t2 = (const uint2*)t;
    float4 bb = __ldg((const float4*)bias + c4);
    int base = blockIdx.x * 128 + wid * 16 + half * 8;
    if (base >= n) return;

    int curg = -1, lc = 0;
    float4 ls = make_float4(0.f, 0.f, 0.f, 0.f);
    float4 lm = make_float4(0.f, 0.f, 0.f, 0.f);

    auto flush = [&]() {
        if (curg >= 0) {
            int o = curg * HID + 4 * c4;
            atomicAdd(&d_gsum[o + 0], ls.x);
            atomicAdd(&d_gsum[o + 1], ls.y);
            atomicAdd(&d_gsum[o + 2], ls.z);
            atomicAdd(&d_gsum[o + 3], ls.w);
            atomicMax(&d_gmax[o + 0], __float_as_uint(lm.x));
            atomicMax(&d_gmax[o + 1], __float_as_uint(lm.y));
            atomicMax(&d_gmax[o + 2], __float_as_uint(lm.z));
            atomicMax(&d_gmax[o + 3], __float_as_uint(lm.w));
            if (c4 == 0) atomicAdd(&d_cnt[curg], lc);
        }
    };

    int icur = base;
    float4 mt = __ldg(&d_metaf[icur]);
    uint2 sv = __ldg(t2 + (size_t)icur * 16 + c4);
    int start = __float_as_int(mt.x), cnt = __float_as_int(mt.y);
    float di = mt.z;
    int idx[4]; float w4[4];
    load4cw(start, cnt, icur, idx, w4);

#pragma unroll 1
    for (int p = 0; p < 8; p++) {
        int i = base + p;
        if (i >= n) break;
        float4 mtn; uint2 svn; int inn = 0;
        bool hasnext = (p < 7) && (i + 1 < n);
        if (hasnext) {
            inn = i + 1;
            mtn = __ldg(&d_metaf[inn]);
            svn = __ldg(t2 + (size_t)inn * 16 + c4);
        }
        int g = ld_idx32(batch, i, is64);
        if (g != curg) {
            flush();
            curg = g; lc = 0;
            ls = make_float4(0.f, 0.f, 0.f, 0.f);
            lm = make_float4(0.f, 0.f, 0.f, 0.f);
        }
        float4 h = agg_body(t2, c4, di, sv, idx, w4, start, cnt, bb);
        ls.x += h.x; ls.y += h.y; ls.z += h.z; ls.w += h.w;
        lm.x = fmaxf(lm.x, h.x); lm.y = fmaxf(lm.y, h.y);
        lm.z = fmaxf(lm.z, h.z); lm.w = fmaxf(lm.w, h.w);
        lc++;
        if (hasnext) {
            start = __float_as_int(mtn.x); cnt = __float_as_int(mtn.y); di = mtn.z;
            sv = svn;
            load4cw(start, cnt, inn, idx, w4);
        }
    }
    flush();
}

// ---------------- final ----------------
__global__ void final_kernel(const float* __restrict__ Wout, const float* __restrict__ bout,
                             float* __restrict__ out) {
    __shared__ float p[2 * HID];
    int g = blockIdx.x;
    int t = threadIdx.x;  // 128
    if (t < HID) {
        float cn = fmaxf((float)d_cnt[g], 1.f);
        p[t] = d_gsum[g * HID + t] / cn;
        p[HID + t] = __uint_as_float(d_gmax[g * HID + t]);
    }
    __syncthreads();
    if (t < NC) {
        float a = bout[t];
#pragma unroll 16
        for (int k = 0; k < 2 * HID; k++) a += p[k] * Wout[k * NC + t];
        out[g * NC + t] = a;
    }
}

// ---------------- launch ----------------
extern "C" void kernel_launch(void* const* d_in, const int* in_sizes, int n_in,
                              void* d_out, int out_size) {
    const float* x    = (const float*)d_in[0];
    const void*  ei   = d_in[1];
    const void*  bat  = d_in[2];
    const float* W0   = (const float*)d_in[3];
    const float* b0   = (const float*)d_in[4];
    const float* W1   = (const float*)d_in[5];
    const float* b1   = (const float*)d_in[6];
    const float* W2   = (const float*)d_in[7];
    const float* b2   = (const float*)d_in[8];
    const float* Wout = (const float*)d_in[9];
    const float* bout = (const float*)d_in[10];
    float* out = (float*)d_out;

    int N = in_sizes[2];
    int E = in_sizes[1] / 2;

    __half *hp, *tp;
    cudaGetSymbolAddress((void**)&hp, d_hbuf);
    cudaGetSymbolAddress((void**)&tp, d_tbuf);

    int fsmem = (2 * 128 * 36 + 2 * 32 * 72) * 4;  // 55296
    cudaFuncSetAttribute(fused_agg_gemm, cudaFuncAttributeMaxDynamicSharedMemorySize, fsmem);

    int gblk = (N + 127) / 128;

    static cudaStream_t s2 = nullptr;
    static cudaEvent_t evFork = nullptr, evJoin = nullptr;
    if (s2 == nullptr) {
        cudaStreamCreateWithFlags(&s2, cudaStreamNonBlocking);
        cudaEventCreateWithFlags(&evFork, cudaEventDisableTiming);
        cudaEventCreateWithFlags(&evJoin, cudaEventDisableTiming);
    }

    // fork: CSR build on s2, layer-0 GEMM on main stream
    cudaEventRecord(evFork, 0);
    cudaStreamWaitEvent(s2, evFork, 0);

    detect_kernel<<<1, 256, 0, s2>>>((const unsigned*)ei);
    zero_kernel<<<(N + 255) / 256, 256, 0, s2>>>(N);
    hist_kernel<<<(E + 255) / 256, 256, 0, s2>>>(ei, E);
    dinv_kernel<<<(N + 255) / 256, 256, 0, s2>>>(N);
    int nb = (N + SCAN_B - 1) / SCAN_B;
    scanA_kernel<<<nb, SCAN_T, 0, s2>>>(N);
    scanB_kernel<<<1, 512, 0, s2>>>(nb);
    scanC_kernel<<<(N + 255) / 256, 256, 0, s2>>>(N);
    scatter_kernel<<<(E + 255) / 256, 256, 0, s2>>>(ei, E);

    gemm_mma128<<<gblk, 256>>>(x, W0, tp, N);

    cudaEventRecord(evJoin, s2);
    cudaStreamWaitEvent(0, evJoin, 0);

    fused_agg_gemm<<<gblk, 256, fsmem>>>(tp, b0, W1, hp, N);
    fused_agg_gemm<<<gblk, 256, fsmem>>>(hp, b1, W2, tp, N);
    fused_agg_pool<<<gblk, 256>>>(tp, b2, bat, N);
    final_kernel<<<NG, 128>>>(Wout, bout, out);
}